// round 14
// baseline (speedup 1.0000x reference)
#include <cuda_runtime.h>
#include <cuda_bf16.h>
#include <mma.h>
#include <cstdint>

using namespace nvcuda;

#define BB 16
#define NN 4096
#define SS 1024
#define NQ (BB*SS)
#define KMAX 64
#define CIN 67
#define CF  64

/* ---------------- scratch (device globals; no allocation allowed) -------- */
__device__ int    g_knn[NQ*KMAX];
__device__ float  g_newxyz[NQ*3];
#define B1OFF0 0
#define B1OFF1 (16384u*16u*64u)
#define B1OFF2 (B1OFF1 + 16384u*32u*64u)
#define B1TOT  (B1OFF2 + 16384u*64u*64u)
__device__ float  g_buf1[B1TOT];
__device__ float  g_buf2[B1TOT];
__device__ float  g_max[(size_t)3*NQ*128];
__device__ float  g_min[(size_t)3*NQ*128];
__device__ double g_sum[3][3][128];   /* [scale][layer][chan] */
__device__ double g_sq[3][3][128];

/* split a,b (fp32) into packed bf16 hi-pair and lo-pair (a in low 16 bits) */
__device__ __forceinline__ void split2(float a, float b, unsigned &hi, unsigned &lo)
{
    __nv_bfloat16 ah = __float2bfloat16(a), bh = __float2bfloat16(b);
    float ar = a - __bfloat162float(ah), br = b - __bfloat162float(bh);
    __nv_bfloat16 al = __float2bfloat16(ar), bl = __float2bfloat16(br);
    hi = (unsigned)__bfloat16_as_ushort(ah) | ((unsigned)__bfloat16_as_ushort(bh) << 16);
    lo = (unsigned)__bfloat16_as_ushort(al) | ((unsigned)__bfloat16_as_ushort(bl) << 16);
}

/* BN scale/shift from raw sums — identical math to the old stats_kernel */
__device__ __forceinline__ void bn_coeff(int s, int layer, int c, double invn,
                                         const float* gamma, const float* beta,
                                         float &scl, float &shf)
{
    double sv = g_sum[s][layer][c], q2 = g_sq[s][layer][c];
    double mu = sv * invn;
    double var = q2 * invn - mu * mu;
    float rstd = rsqrtf((float)var + 1e-5f);
    scl = gamma[c] * rstd;
    shf = beta[c] - (float)mu * scl;
}

/* --------------------------- init ---------------------------------------- */
__global__ void init_kernel()
{
    int t = threadIdx.x;
    if (t < 128) {
#pragma unroll
        for (int s = 0; s < 3; s++)
#pragma unroll
            for (int l = 0; l < 3; l++) {
                g_sum[s][l][t] = 0.0;
                g_sq[s][l][t]  = 0.0;
            }
    }
}

/* ------------------------------- FPS ------------------------------------ */
__global__ void __launch_bounds__(1024) fps_kernel(const float* __restrict__ xyz,
                                                   float* __restrict__ out_newxyz)
{
    const int b = blockIdx.x;
    const int t = threadIdx.x;
    const int lane = t & 31, wid = t >> 5;
    const float* X = xyz + (size_t)b*NN*3;

    float px[4], py[4], pz[4], dd[4];
#pragma unroll
    for (int j = 0; j < 4; j++) {
        int p = t + 1024*j;
        px[j] = X[p*3+0]; py[j] = X[p*3+1]; pz[j] = X[p*3+2];
        dd[j] = 1e10f;
    }
    __shared__ unsigned long long wb[32];
    int far = 0;

    for (int it = 0; it < SS; ++it) {
        float cx = X[far*3+0], cy = X[far*3+1], cz = X[far*3+2];
        if (t == 0) {
            int o = b*SS + it;
            out_newxyz[o*3+0] = cx; out_newxyz[o*3+1] = cy; out_newxyz[o*3+2] = cz;
            g_newxyz[o*3+0]  = cx; g_newxyz[o*3+1]  = cy; g_newxyz[o*3+2]  = cz;
        }
        unsigned long long best = 0ull;
#pragma unroll
        for (int j = 0; j < 4; j++) {
            float dx = px[j]-cx, dy = py[j]-cy, dz = pz[j]-cz;
            float d  = fmaf(dz, dz, fmaf(dy, dy, dx*dx));
            dd[j] = fminf(dd[j], d);
            int p = t + 1024*j;
            unsigned long long key =
                (((unsigned long long)__float_as_uint(dd[j])) << 32) | (unsigned)(NN-1-p);
            best = (key > best) ? key : best;
        }
#pragma unroll
        for (int o = 16; o; o >>= 1) {
            unsigned long long v = __shfl_xor_sync(0xffffffffu, best, o);
            if (v > best) best = v;
        }
        if (lane == 0) wb[wid] = best;
        __syncthreads();
        unsigned long long v = wb[lane];
#pragma unroll
        for (int o = 16; o; o >>= 1) {
            unsigned long long u = __shfl_xor_sync(0xffffffffu, v, o);
            if (u > v) v = u;
        }
        far = NN - 1 - (int)(v & 0xffffffffu);
        __syncthreads();
    }
}

/* ------------------- kNN: O(N) radix-select + bitonic -------------------- */
__device__ __forceinline__ unsigned mono_f32(float v)
{
    unsigned u = __float_as_uint(v);
    return (u & 0x80000000u) ? ~u : (u | 0x80000000u);
}

__global__ void __launch_bounds__(128) knn_kernel(const float* __restrict__ xyz)
{
    const int q = blockIdx.x;
    const int b = q >> 10;
    const int t = threadIdx.x;
    const int lane = t & 31;
    __shared__ unsigned hist[256];
    __shared__ unsigned long long arr[64];
    __shared__ unsigned long long s_K;
    __shared__ int s_bin, s_r, s_cnt, s_pos;
    const float* X = xyz + (size_t)b*NN*3;

    const float qx = g_newxyz[q*3+0], qy = g_newxyz[q*3+1], qz = g_newxyz[q*3+2];
    const float qq = qx*qx + qy*qy + qz*qz;

    unsigned mk[32];
#pragma unroll 8
    for (int i = 0; i < 32; i++) {
        int p = t + 128*i;
        float x = X[p*3+0], y = X[p*3+1], z = X[p*3+2];
        float pp  = x*x + y*y + z*z;
        float dot = qx*x + qy*y + qz*z;
        float d2  = qq + pp - 2.0f*dot;
        mk[i] = mono_f32(d2);
    }

    unsigned long long prefix = 0ull, pmask = 0ull;
    int r = KMAX;
    for (int shift = 56; shift >= 0; shift -= 8) {
        hist[t] = 0u; hist[t+128] = 0u;
        __syncthreads();
#pragma unroll 8
        for (int i = 0; i < 32; i++) {
            unsigned long long k = ((unsigned long long)mk[i] << 32) | (unsigned)(t + 128*i);
            if ((k & pmask) == prefix)
                atomicAdd(&hist[(unsigned)(k >> shift) & 255u], 1u);
        }
        __syncthreads();
        if (t < 32) {
            unsigned part = 0;
#pragma unroll
            for (int i = 0; i < 8; i++) part += hist[t*8 + i];
            unsigned cum = part;
#pragma unroll
            for (int o = 1; o < 32; o <<= 1) {
                unsigned v = __shfl_up_sync(0xffffffffu, cum, o);
                if (lane >= o) cum += v;
            }
            unsigned cb = cum - part;
            bool has = (cb < (unsigned)r) && ((unsigned)r <= cum);
            unsigned mball = __ballot_sync(0xffffffffu, has);
            if (t == __ffs(mball) - 1) {
                int rr = r - (int)cb;
                int bb = t*8;
                for (;;) {
                    unsigned h = hist[bb];
                    if (rr <= (int)h) { s_cnt = (int)h; break; }
                    rr -= (int)h; bb++;
                }
                s_bin = bb; s_r = rr;
            }
        }
        __syncthreads();
        prefix |= ((unsigned long long)(unsigned)s_bin) << shift;
        pmask  |= (255ull << shift);
        r = s_r;
        int cnt = s_cnt;
        __syncthreads();
        if (cnt == 1) break;
    }

#pragma unroll 8
    for (int i = 0; i < 32; i++) {
        unsigned long long k = ((unsigned long long)mk[i] << 32) | (unsigned)(t + 128*i);
        if ((k & pmask) == prefix) s_K = k;
    }
    if (t == 0) s_pos = 0;
    __syncthreads();
    const unsigned long long K64 = s_K;

#pragma unroll 8
    for (int i = 0; i < 32; i++) {
        unsigned long long k = ((unsigned long long)mk[i] << 32) | (unsigned)(t + 128*i);
        if (k <= K64) {
            int pos = atomicAdd(&s_pos, 1);
            arr[pos] = k;
        }
    }
    __syncthreads();

    for (int k2 = 2; k2 <= 64; k2 <<= 1)
        for (int j = k2 >> 1; j > 0; j >>= 1) {
            if (t < 64) {
                int ixj = t ^ j;
                if (ixj > t) {
                    unsigned long long a = arr[t], c = arr[ixj];
                    bool up = ((t & k2) == 0);
                    if ((a > c) == up) { arr[t] = c; arr[ixj] = a; }
                }
            }
            __syncthreads();
        }

    if (t < 64) g_knn[q*KMAX + t] = (int)(arr[t] & 0xffffffffu);
}

/* ================== WMMA bf16 (hi/lo split) conv kernels ================= */
/* 128-row tiles, 256 threads; single-loop 3-term MMA; fused epilogues      */
#define LD1 88
#define LD2 72

/* ---- conv1: gather+concat + 80->64 --------------------------------------*/
__global__ void __launch_bounds__(256, 2) conv1_mma(const float* __restrict__ xyz,
                                                    const float* __restrict__ feat,
                                                    const float* __restrict__ W,
                                                    int lgk, int s, unsigned boff)
{
    extern __shared__ char dyn[];
    __nv_bfloat16* Ah = (__nv_bfloat16*)dyn;          /* [128][LD1] */
    __nv_bfloat16* Al = Ah + 128*LD1;
    __nv_bfloat16* Bh = Al + 128*LD1;                 /* [64][LD1]  */
    __nv_bfloat16* Bl = Bh + 64*LD1;
    float* Cs = (float*)dyn;                          /* reuse: [128][64] */
    __shared__ float ps[8][64], pq[8][64];

    const int t = threadIdx.x, tile = blockIdx.x;
    const int wid = t >> 5;

    {
        const int r = t >> 1, sub = t & 1;
        const int gr = tile*128 + r;
        const int q  = gr >> lgk;
        const int j  = gr & ((1 << lgk) - 1);
        const int n  = g_knn[q*KMAX + j];
        const int b  = q >> 10;
        const float* fp = feat + (size_t)(b*NN + n)*CF;
        unsigned* ah = (unsigned*)(Ah + r*LD1);
        unsigned* al = (unsigned*)(Al + r*LD1);
#pragma unroll
        for (int jj = sub*8; jj < sub*8 + 8; jj++) {
            float4 v = *(const float4*)(fp + jj*4);
            unsigned h0, l0, h1, l1;
            split2(v.x, v.y, h0, l0); split2(v.z, v.w, h1, l1);
            ah[jj*2]   = h0; ah[jj*2+1] = h1;
            al[jj*2]   = l0; al[jj*2+1] = l1;
        }
        if (sub) {
            const float* xp = xyz + (size_t)(b*NN + n)*3;
            float dx = xp[0]-g_newxyz[q*3+0], dy = xp[1]-g_newxyz[q*3+1], dz = xp[2]-g_newxyz[q*3+2];
            unsigned h0, l0, h1, l1;
            split2(dx, dy, h0, l0); split2(dz, 0.f, h1, l1);
            ah[32] = h0; ah[33] = h1; al[32] = l0; al[33] = l1;
#pragma unroll
            for (int z = 34; z < 40; z++) { ah[z] = 0u; al[z] = 0u; }
        }
    }
    if (t < 128) {
        const int n = t >> 1, sub = t & 1;
        const float* w = W + n*CIN;
        unsigned* bh = (unsigned*)(Bh + n*LD1);
        unsigned* bl = (unsigned*)(Bl + n*LD1);
#pragma unroll
        for (int jj = sub*16; jj < sub*16 + 16; jj++) {
            unsigned h, l;
            split2(w[3 + jj*2], w[3 + jj*2 + 1], h, l);
            bh[jj] = h; bl[jj] = l;
        }
        if (sub) {
            unsigned h0, l0, h1, l1;
            split2(w[0], w[1], h0, l0); split2(w[2], 0.f, h1, l1);
            bh[32] = h0; bh[33] = h1; bl[32] = l0; bl[33] = l1;
#pragma unroll
            for (int z = 34; z < 40; z++) { bh[z] = 0u; bl[z] = 0u; }
        }
    }
    __syncthreads();

    const int rowg = wid >> 1, colg = wid & 1;
    wmma::fragment<wmma::accumulator, 16, 16, 16, float> acc[2][2];
#pragma unroll
    for (int i = 0; i < 2; i++)
#pragma unroll
        for (int j = 0; j < 2; j++) wmma::fill_fragment(acc[i][j], 0.f);

    /* single loop: per kstep load Ah,Al once; terms hh + lh + hl */
#pragma unroll
    for (int ks = 0; ks < 5; ks++) {
        wmma::fragment<wmma::matrix_a, 16, 16, 16, __nv_bfloat16, wmma::row_major> afh[2], afl[2];
        wmma::fragment<wmma::matrix_b, 16, 16, 16, __nv_bfloat16, wmma::col_major> bfh[2], bfl[2];
#pragma unroll
        for (int i = 0; i < 2; i++) {
            wmma::load_matrix_sync(afh[i], Ah + (rowg*32 + i*16)*LD1 + ks*16, LD1);
            wmma::load_matrix_sync(afl[i], Al + (rowg*32 + i*16)*LD1 + ks*16, LD1);
        }
#pragma unroll
        for (int j = 0; j < 2; j++)
            wmma::load_matrix_sync(bfh[j], Bh + (colg*32 + j*16)*LD1 + ks*16, LD1);
#pragma unroll
        for (int i = 0; i < 2; i++)
#pragma unroll
            for (int j = 0; j < 2; j++) {
                wmma::mma_sync(acc[i][j], afh[i], bfh[j], acc[i][j]);
                wmma::mma_sync(acc[i][j], afl[i], bfh[j], acc[i][j]);
            }
#pragma unroll
        for (int j = 0; j < 2; j++)
            wmma::load_matrix_sync(bfl[j], Bl + (colg*32 + j*16)*LD1 + ks*16, LD1);
#pragma unroll
        for (int i = 0; i < 2; i++)
#pragma unroll
            for (int j = 0; j < 2; j++)
                wmma::mma_sync(acc[i][j], afh[i], bfl[j], acc[i][j]);
    }
    __syncthreads();
#pragma unroll
    for (int i = 0; i < 2; i++)
#pragma unroll
        for (int j = 0; j < 2; j++)
            wmma::store_matrix_sync(Cs + (rowg*32 + i*16)*64 + colg*32 + j*16,
                                    acc[i][j], 64, wmma::mem_row_major);
    __syncthreads();

    /* fused copy + stats: columns per thread are fixed ((t*4)&63) */
    {
        float* bufOut = g_buf1 + boff;
        const size_t base = (size_t)tile*128*64;
        float sv[4] = {0,0,0,0}, qv[4] = {0,0,0,0};
        for (int i = t*4; i < 128*64; i += 1024) {
            float4 v = *(const float4*)(Cs + i);
            *(float4*)(bufOut + base + i) = v;
            sv[0] += v.x; qv[0] = fmaf(v.x, v.x, qv[0]);
            sv[1] += v.y; qv[1] = fmaf(v.y, v.y, qv[1]);
            sv[2] += v.z; qv[2] = fmaf(v.z, v.z, qv[2]);
            sv[3] += v.w; qv[3] = fmaf(v.w, v.w, qv[3]);
        }
#pragma unroll
        for (int c = 0; c < 4; c++) {
            sv[c] += __shfl_xor_sync(0xffffffffu, sv[c], 16);
            qv[c] += __shfl_xor_sync(0xffffffffu, qv[c], 16);
        }
        if ((t & 31) < 16) {
            const int cg = (t & 15) * 4;
#pragma unroll
            for (int c = 0; c < 4; c++) { ps[wid][cg+c] = sv[c]; pq[wid][cg+c] = qv[c]; }
        }
    }
    __syncthreads();
    if (t < 64) {
        float S = 0.f, Q = 0.f;
#pragma unroll
        for (int w = 0; w < 8; w++) { S += ps[w][t]; Q += pq[w][t]; }
        atomicAdd(&g_sum[s][0][t], (double)S);
        atomicAdd(&g_sq[s][0][t],  (double)Q);
    }
}

/* ---- conv2: BN+ReLU load + 64->64 ---------------------------------------*/
__global__ void __launch_bounds__(256, 2) conv2_mma(const float* __restrict__ W,
                                                    const float* __restrict__ gamma,
                                                    const float* __restrict__ beta,
                                                    double invn, int s, unsigned boff)
{
    extern __shared__ char dyn[];
    __nv_bfloat16* Ah = (__nv_bfloat16*)dyn;
    __nv_bfloat16* Al = Ah + 128*LD2;
    __nv_bfloat16* Bh = Al + 128*LD2;
    __nv_bfloat16* Bl = Bh + 64*LD2;
    float* Cs = (float*)dyn;
    __shared__ float sc[64], sh[64], ps[8][64], pq[8][64];

    const int t = threadIdx.x, tile = blockIdx.x;
    const int wid = t >> 5;

    if (t < 64) bn_coeff(s, 0, t, invn, gamma, beta, sc[t], sh[t]);
    __syncthreads();

    {
        const int r = t >> 1, sub = t & 1;
        const float* ip = g_buf1 + boff + ((size_t)tile*128 + r)*64;
        unsigned* ah = (unsigned*)(Ah + r*LD2);
        unsigned* al = (unsigned*)(Al + r*LD2);
#pragma unroll
        for (int jj = sub*8; jj < sub*8 + 8; jj++) {
            float4 v = *(const float4*)(ip + jj*4);
            int c0 = jj*4;
            float a = fmaxf(fmaf(v.x, sc[c0+0], sh[c0+0]), 0.f);
            float b = fmaxf(fmaf(v.y, sc[c0+1], sh[c0+1]), 0.f);
            float c = fmaxf(fmaf(v.z, sc[c0+2], sh[c0+2]), 0.f);
            float d = fmaxf(fmaf(v.w, sc[c0+3], sh[c0+3]), 0.f);
            unsigned h0, l0, h1, l1;
            split2(a, b, h0, l0); split2(c, d, h1, l1);
            ah[jj*2] = h0; ah[jj*2+1] = h1;
            al[jj*2] = l0; al[jj*2+1] = l1;
        }
    }
    if (t < 128) {
        const int n = t >> 1, sub = t & 1;
        const float* w = W + n*64;
        unsigned* bh = (unsigned*)(Bh + n*LD2);
        unsigned* bl = (unsigned*)(Bl + n*LD2);
#pragma unroll
        for (int jj = sub*8; jj < sub*8 + 8; jj++) {
            float4 v = *(const float4*)(w + jj*4);
            unsigned h0, l0, h1, l1;
            split2(v.x, v.y, h0, l0); split2(v.z, v.w, h1, l1);
            bh[jj*2] = h0; bh[jj*2+1] = h1;
            bl[jj*2] = l0; bl[jj*2+1] = l1;
        }
    }
    __syncthreads();

    const int rowg = wid >> 1, colg = wid & 1;
    wmma::fragment<wmma::accumulator, 16, 16, 16, float> acc[2][2];
#pragma unroll
    for (int i = 0; i < 2; i++)
#pragma unroll
        for (int j = 0; j < 2; j++) wmma::fill_fragment(acc[i][j], 0.f);

#pragma unroll
    for (int ks = 0; ks < 4; ks++) {
        wmma::fragment<wmma::matrix_a, 16, 16, 16, __nv_bfloat16, wmma::row_major> afh[2], afl[2];
        wmma::fragment<wmma::matrix_b, 16, 16, 16, __nv_bfloat16, wmma::col_major> bfh[2], bfl[2];
#pragma unroll
        for (int i = 0; i < 2; i++) {
            wmma::load_matrix_sync(afh[i], Ah + (rowg*32 + i*16)*LD2 + ks*16, LD2);
            wmma::load_matrix_sync(afl[i], Al + (rowg*32 + i*16)*LD2 + ks*16, LD2);
        }
#pragma unroll
        for (int j = 0; j < 2; j++)
            wmma::load_matrix_sync(bfh[j], Bh + (colg*32 + j*16)*LD2 + ks*16, LD2);
#pragma unroll
        for (int i = 0; i < 2; i++)
#pragma unroll
            for (int j = 0; j < 2; j++) {
                wmma::mma_sync(acc[i][j], afh[i], bfh[j], acc[i][j]);
                wmma::mma_sync(acc[i][j], afl[i], bfh[j], acc[i][j]);
            }
#pragma unroll
        for (int j = 0; j < 2; j++)
            wmma::load_matrix_sync(bfl[j], Bl + (colg*32 + j*16)*LD2 + ks*16, LD2);
#pragma unroll
        for (int i = 0; i < 2; i++)
#pragma unroll
            for (int j = 0; j < 2; j++)
                wmma::mma_sync(acc[i][j], afh[i], bfl[j], acc[i][j]);
    }
    __syncthreads();
#pragma unroll
    for (int i = 0; i < 2; i++)
#pragma unroll
        for (int j = 0; j < 2; j++)
            wmma::store_matrix_sync(Cs + (rowg*32 + i*16)*64 + colg*32 + j*16,
                                    acc[i][j], 64, wmma::mem_row_major);
    __syncthreads();

    {
        float* bufOut = g_buf2 + boff;
        const size_t base = (size_t)tile*128*64;
        float sv[4] = {0,0,0,0}, qv[4] = {0,0,0,0};
        for (int i = t*4; i < 128*64; i += 1024) {
            float4 v = *(const float4*)(Cs + i);
            *(float4*)(bufOut + base + i) = v;
            sv[0] += v.x; qv[0] = fmaf(v.x, v.x, qv[0]);
            sv[1] += v.y; qv[1] = fmaf(v.y, v.y, qv[1]);
            sv[2] += v.z; qv[2] = fmaf(v.z, v.z, qv[2]);
            sv[3] += v.w; qv[3] = fmaf(v.w, v.w, qv[3]);
        }
#pragma unroll
        for (int c = 0; c < 4; c++) {
            sv[c] += __shfl_xor_sync(0xffffffffu, sv[c], 16);
            qv[c] += __shfl_xor_sync(0xffffffffu, qv[c], 16);
        }
        if ((t & 31) < 16) {
            const int cg = (t & 15) * 4;
#pragma unroll
            for (int c = 0; c < 4; c++) { ps[wid][cg+c] = sv[c]; pq[wid][cg+c] = qv[c]; }
        }
    }
    __syncthreads();
    if (t < 64) {
        float S = 0.f, Q = 0.f;
#pragma unroll
        for (int w = 0; w < 8; w++) { S += ps[w][t]; Q += pq[w][t]; }
        atomicAdd(&g_sum[s][1][t], (double)S);
        atomicAdd(&g_sq[s][1][t],  (double)Q);
    }
}

/* ---- conv3: BN+ReLU load + 64->128 + fused stats/max/min ---------------- */
template<int K>
__global__ void __launch_bounds__(256, 2) conv3_mma(const float* __restrict__ W,
                                                    const float* __restrict__ gamma,
                                                    const float* __restrict__ beta,
                                                    double invn, int s, unsigned boff)
{
    extern __shared__ char dyn[];
    __nv_bfloat16* Ah = (__nv_bfloat16*)dyn;
    __nv_bfloat16* Al = Ah + 128*LD2;
    __nv_bfloat16* Bh = Al + 128*LD2;
    __nv_bfloat16* Bl = Bh + 128*LD2;
    float* Cs = (float*)dyn;                          /* [128][128] */
    __shared__ float sc[64], sh[64], ps[2][128], pq[2][128];

    const int t = threadIdx.x, tile = blockIdx.x;
    const int wid = t >> 5;

    if (t < 64) bn_coeff(s, 1, t, invn, gamma, beta, sc[t], sh[t]);
    __syncthreads();

    {
        const int r = t >> 1, sub = t & 1;
        const float* ip = g_buf2 + boff + ((size_t)tile*128 + r)*64;
        unsigned* ah = (unsigned*)(Ah + r*LD2);
        unsigned* al = (unsigned*)(Al + r*LD2);
#pragma unroll
        for (int jj = sub*8; jj < sub*8 + 8; jj++) {
            float4 v = *(const float4*)(ip + jj*4);
            int c0 = jj*4;
            float a = fmaxf(fmaf(v.x, sc[c0+0], sh[c0+0]), 0.f);
            float b = fmaxf(fmaf(v.y, sc[c0+1], sh[c0+1]), 0.f);
            float c = fmaxf(fmaf(v.z, sc[c0+2], sh[c0+2]), 0.f);
            float d = fmaxf(fmaf(v.w, sc[c0+3], sh[c0+3]), 0.f);
            unsigned h0, l0, h1, l1;
            split2(a, b, h0, l0); split2(c, d, h1, l1);
            ah[jj*2] = h0; ah[jj*2+1] = h1;
            al[jj*2] = l0; al[jj*2+1] = l1;
        }
    }
    {
        const int n = t >> 1, sub = t & 1;
        const float* w = W + (size_t)n*64;
        unsigned* bh = (unsigned*)(Bh + n*LD2);
        unsigned* bl = (unsigned*)(Bl + n*LD2);
#pragma unroll
        for (int jj = sub*8; jj < sub*8 + 8; jj++) {
            float4 v = *(const float4*)(w + jj*4);
            unsigned h0, l0, h1, l1;
            split2(v.x, v.y, h0, l0); split2(v.z, v.w, h1, l1);
            bh[jj*2] = h0; bh[jj*2+1] = h1;
            bl[jj*2] = l0; bl[jj*2+1] = l1;
        }
    }
    __syncthreads();

    const int rowg = wid >> 1, colg = wid & 1;
    wmma::fragment<wmma::accumulator, 16, 16, 16, float> acc[2][4];
#pragma unroll
    for (int i = 0; i < 2; i++)
#pragma unroll
        for (int j = 0; j < 4; j++) wmma::fill_fragment(acc[i][j], 0.f);

#pragma unroll
    for (int ks = 0; ks < 4; ks++) {
        wmma::fragment<wmma::matrix_a, 16, 16, 16, __nv_bfloat16, wmma::row_major> afh[2], afl[2];
#pragma unroll
        for (int i = 0; i < 2; i++) {
            wmma::load_matrix_sync(afh[i], Ah + (rowg*32 + i*16)*LD2 + ks*16, LD2);
            wmma::load_matrix_sync(afl[i], Al + (rowg*32 + i*16)*LD2 + ks*16, LD2);
        }
#pragma unroll
        for (int j = 0; j < 4; j++) {
            wmma::fragment<wmma::matrix_b, 16, 16, 16, __nv_bfloat16, wmma::col_major> bf;
            wmma::load_matrix_sync(bf, Bh + (colg*64 + j*16)*LD2 + ks*16, LD2);
#pragma unroll
            for (int i = 0; i < 2; i++) {
                wmma::mma_sync(acc[i][j], afh[i], bf, acc[i][j]);
                wmma::mma_sync(acc[i][j], afl[i], bf, acc[i][j]);
            }
        }
#pragma unroll
        for (int j = 0; j < 4; j++) {
            wmma::fragment<wmma::matrix_b, 16, 16, 16, __nv_bfloat16, wmma::col_major> bf;
            wmma::load_matrix_sync(bf, Bl + (colg*64 + j*16)*LD2 + ks*16, LD2);
#pragma unroll
            for (int i = 0; i < 2; i++)
                wmma::mma_sync(acc[i][j], afh[i], bf, acc[i][j]);
        }
    }
    __syncthreads();
#pragma unroll
    for (int i = 0; i < 2; i++)
#pragma unroll
        for (int j = 0; j < 4; j++)
            wmma::store_matrix_sync(Cs + (rowg*32 + i*16)*128 + colg*64 + j*16,
                                    acc[i][j], 128, wmma::mem_row_major);
    __syncthreads();

    /* fused stats + per-query max/min (each (c,g) covers its qi rows) */
    {
        const int c = t & 127, g = t >> 7;
        const int nq_tile = 128 / K;
        float* gmax = g_max + (size_t)s*NQ*128;
        float* gmin = g_min + (size_t)s*NQ*128;
        float sv = 0.f, qv = 0.f;
        for (int qi = g; qi < nq_tile; qi += 2) {
            float mx = -3.4e38f, mn = 3.4e38f;
#pragma unroll 8
            for (int r0 = 0; r0 < K; r0++) {
                float v = Cs[(qi*K + r0)*128 + c];
                mx = fmaxf(mx, v); mn = fminf(mn, v);
                sv += v; qv = fmaf(v, v, qv);
            }
            const int q = tile*nq_tile + qi;
            gmax[q*128 + c] = mx;
            gmin[q*128 + c] = mn;
        }
        ps[g][c] = sv; pq[g][c] = qv;
    }
    __syncthreads();
    if (t < 128) {
        atomicAdd(&g_sum[s][2][t], (double)(ps[0][t] + ps[1][t]));
        atomicAdd(&g_sq[s][2][t],  (double)(pq[0][t] + pq[1][t]));
    }
}

/* -------- finalize: BN(+sign-aware max/min) + ReLU -> out ---------------- */
__global__ void __launch_bounds__(128) finalize_kernel(float* __restrict__ out,
                                                       const float* __restrict__ gamma,
                                                       const float* __restrict__ beta,
                                                       double invn, int s)
{
    const int q = blockIdx.x;
    const int c = threadIdx.x;
    float scl, shf;
    bn_coeff(s, 2, c, invn, gamma, beta, scl, shf);
    const float* gmax = g_max + (size_t)s*NQ*128;
    const float* gmin = g_min + (size_t)s*NQ*128;
    float sel = (scl >= 0.f) ? gmax[q*128 + c] : gmin[q*128 + c];
    out[(size_t)NQ*3 + (size_t)q*384 + s*128 + c] = fmaxf(fmaf(sel, scl, shf), 0.f);
}

/* ------------------------------ driver ----------------------------------- */
extern "C" void kernel_launch(void* const* d_in, const int* in_sizes, int n_in,
                              void* d_out, int out_size)
{
    const float* xyz  = (const float*)d_in[0];
    const float* feat = (const float*)d_in[1];
    const float* w0   = (const float*)d_in[2];
    const float* w1   = (const float*)d_in[3];
    const float* w2   = (const float*)d_in[4];
    const float* g0   = (const float*)d_in[5];
    const float* g1   = (const float*)d_in[6];
    const float* g2   = (const float*)d_in[7];
    const float* b0   = (const float*)d_in[8];
    const float* b1   = (const float*)d_in[9];
    const float* b2   = (const float*)d_in[10];
    float* out = (float*)d_out;

    const int SM1 = (2*128*LD1 + 2*64*LD1) * 2;     /* 67584 */
    const int SM2 = (2*128*LD2 + 2*64*LD2) * 2;     /* 55296 */
    const int SM3 = (2*128*LD2 + 2*128*LD2) * 2;    /* 73728 */
    cudaFuncSetAttribute(conv1_mma, cudaFuncAttributeMaxDynamicSharedMemorySize, SM1);
    cudaFuncSetAttribute(conv2_mma, cudaFuncAttributeMaxDynamicSharedMemorySize, SM2);
    cudaFuncSetAttribute(conv3_mma<16>, cudaFuncAttributeMaxDynamicSharedMemorySize, SM3);
    cudaFuncSetAttribute(conv3_mma<32>, cudaFuncAttributeMaxDynamicSharedMemorySize, SM3);
    cudaFuncSetAttribute(conv3_mma<64>, cudaFuncAttributeMaxDynamicSharedMemorySize, SM3);

    init_kernel<<<1, 128>>>();
    fps_kernel<<<BB, 1024>>>(xyz, out);
    knn_kernel<<<NQ, 128>>>(xyz);

    const int      KS[3]  = {16, 32, 64};
    const int      LGK[3] = {4, 5, 6};
    const unsigned OFF[3] = {B1OFF0, B1OFF1, B1OFF2};

    for (int s = 0; s < 3; s++) {
        const int k = KS[s];
        const int R = NQ * k;
        const double invn = 1.0 / (double)R;

        conv1_mma<<<R/128, 256, SM1>>>(xyz, feat, w0 + (size_t)s*64*CIN, LGK[s], s, OFF[s]);
        conv2_mma<<<R/128, 256, SM2>>>(w1 + (size_t)s*64*64, g0 + s*64, b0 + s*64,
                                       invn, s, OFF[s]);
        if (k == 16)
            conv3_mma<16><<<R/128, 256, SM3>>>(w2 + (size_t)s*128*64, g1 + s*64, b1 + s*64,
                                               invn, s, OFF[s]);
        else if (k == 32)
            conv3_mma<32><<<R/128, 256, SM3>>>(w2 + (size_t)s*128*64, g1 + s*64, b1 + s*64,
                                               invn, s, OFF[s]);
        else
            conv3_mma<64><<<R/128, 256, SM3>>>(w2 + (size_t)s*128*64, g1 + s*64, b1 + s*64,
                                               invn, s, OFF[s]);
        finalize_kernel<<<NQ, 128>>>(out, g2 + s*128, b2 + s*128, invn, s);
    }
}

// round 15
// speedup vs baseline: 1.0260x; 1.0260x over previous
#include <cuda_runtime.h>
#include <cuda_bf16.h>
#include <mma.h>
#include <cstdint>

using namespace nvcuda;

#define BB 16
#define NN 4096
#define SS 1024
#define NQ (BB*SS)
#define KMAX 64
#define CIN 67
#define CF  64

/* ---------------- scratch (device globals; no allocation allowed) -------- */
__device__ int    g_knn[NQ*KMAX];
__device__ float  g_newxyz[NQ*3];
#define B1OFF0 0
#define B1OFF1 (16384u*16u*64u)
#define B1OFF2 (B1OFF1 + 16384u*32u*64u)
#define B1TOT  (B1OFF2 + 16384u*64u*64u)
__device__ float  g_buf1[B1TOT];
__device__ float  g_buf2[B1TOT];
__device__ float  g_max[(size_t)3*NQ*128];
__device__ float  g_min[(size_t)3*NQ*128];
__device__ double g_sum[3][3][128];   /* [scale][layer][chan] */
__device__ double g_sq[3][3][128];

/* split a,b (fp32) into packed bf16 hi-pair and lo-pair (a in low 16 bits) */
__device__ __forceinline__ void split2(float a, float b, unsigned &hi, unsigned &lo)
{
    __nv_bfloat16 ah = __float2bfloat16(a), bh = __float2bfloat16(b);
    float ar = a - __bfloat162float(ah), br = b - __bfloat162float(bh);
    __nv_bfloat16 al = __float2bfloat16(ar), bl = __float2bfloat16(br);
    hi = (unsigned)__bfloat16_as_ushort(ah) | ((unsigned)__bfloat16_as_ushort(bh) << 16);
    lo = (unsigned)__bfloat16_as_ushort(al) | ((unsigned)__bfloat16_as_ushort(bl) << 16);
}

/* BN scale/shift from raw sums — identical math to the old stats_kernel */
__device__ __forceinline__ void bn_coeff(int s, int layer, int c, double invn,
                                         const float* gamma, const float* beta,
                                         float &scl, float &shf)
{
    double sv = g_sum[s][layer][c], q2 = g_sq[s][layer][c];
    double mu = sv * invn;
    double var = q2 * invn - mu * mu;
    float rstd = rsqrtf((float)var + 1e-5f);
    scl = gamma[c] * rstd;
    shf = beta[c] - (float)mu * scl;
}

/* --------------------------- init ---------------------------------------- */
__global__ void init_kernel()
{
    int t = threadIdx.x;
    if (t < 128) {
#pragma unroll
        for (int s = 0; s < 3; s++)
#pragma unroll
            for (int l = 0; l < 3; l++) {
                g_sum[s][l][t] = 0.0;
                g_sq[s][l][t]  = 0.0;
            }
    }
}

/* ------------------------------- FPS (single barrier/iter) --------------- */
__global__ void __launch_bounds__(1024) fps_kernel(const float* __restrict__ xyz,
                                                   float* __restrict__ out_newxyz)
{
    const int b = blockIdx.x;
    const int t = threadIdx.x;
    const int lane = t & 31, wid = t >> 5;
    const float* X = xyz + (size_t)b*NN*3;

    float px[4], py[4], pz[4], dd[4];
#pragma unroll
    for (int j = 0; j < 4; j++) {
        int p = t + 1024*j;
        px[j] = X[p*3+0]; py[j] = X[p*3+1]; pz[j] = X[p*3+2];
        dd[j] = 1e10f;
    }
    __shared__ unsigned long long wb[2][32];
    int far = 0;

    for (int it = 0; it < SS; ++it) {
        const int par = it & 1;
        float cx = X[far*3+0], cy = X[far*3+1], cz = X[far*3+2];
        if (t == 0) {
            int o = b*SS + it;
            out_newxyz[o*3+0] = cx; out_newxyz[o*3+1] = cy; out_newxyz[o*3+2] = cz;
            g_newxyz[o*3+0]  = cx; g_newxyz[o*3+1]  = cy; g_newxyz[o*3+2]  = cz;
        }
        unsigned long long best = 0ull;
#pragma unroll
        for (int j = 0; j < 4; j++) {
            float dx = px[j]-cx, dy = py[j]-cy, dz = pz[j]-cz;
            float d  = fmaf(dz, dz, fmaf(dy, dy, dx*dx));
            dd[j] = fminf(dd[j], d);
            int p = t + 1024*j;
            unsigned long long key =
                (((unsigned long long)__float_as_uint(dd[j])) << 32) | (unsigned)(NN-1-p);
            best = (key > best) ? key : best;
        }
#pragma unroll
        for (int o = 16; o; o >>= 1) {
            unsigned long long v = __shfl_xor_sync(0xffffffffu, best, o);
            if (v > best) best = v;
        }
        if (lane == 0) wb[par][wid] = best;
        __syncthreads();
        unsigned long long v = wb[par][lane];
#pragma unroll
        for (int o = 16; o; o >>= 1) {
            unsigned long long u = __shfl_xor_sync(0xffffffffu, v, o);
            if (u > v) v = u;
        }
        far = NN - 1 - (int)(v & 0xffffffffu);
        /* no trailing barrier: next iteration writes wb[par^1] */
    }
}

/* ------------------- kNN: O(N) radix-select + bitonic -------------------- */
__device__ __forceinline__ unsigned mono_f32(float v)
{
    unsigned u = __float_as_uint(v);
    return (u & 0x80000000u) ? ~u : (u | 0x80000000u);
}

__global__ void __launch_bounds__(128) knn_kernel(const float* __restrict__ xyz)
{
    const int q = blockIdx.x;
    const int b = q >> 10;
    const int t = threadIdx.x;
    const int lane = t & 31;
    __shared__ unsigned hist[256];
    __shared__ unsigned long long arr[64];
    __shared__ unsigned long long s_K;
    __shared__ int s_bin, s_r, s_cnt, s_pos;
    const float* X = xyz + (size_t)b*NN*3;

    const float qx = g_newxyz[q*3+0], qy = g_newxyz[q*3+1], qz = g_newxyz[q*3+2];
    const float qq = qx*qx + qy*qy + qz*qz;

    unsigned mk[32];
#pragma unroll 8
    for (int i = 0; i < 32; i++) {
        int p = t + 128*i;
        float x = X[p*3+0], y = X[p*3+1], z = X[p*3+2];
        float pp  = x*x + y*y + z*z;
        float dot = qx*x + qy*y + qz*z;
        float d2  = qq + pp - 2.0f*dot;
        mk[i] = mono_f32(d2);
    }

    unsigned long long prefix = 0ull, pmask = 0ull;
    int r = KMAX;
    for (int shift = 56; shift >= 0; shift -= 8) {
        hist[t] = 0u; hist[t+128] = 0u;
        __syncthreads();
#pragma unroll 8
        for (int i = 0; i < 32; i++) {
            unsigned long long k = ((unsigned long long)mk[i] << 32) | (unsigned)(t + 128*i);
            if ((k & pmask) == prefix)
                atomicAdd(&hist[(unsigned)(k >> shift) & 255u], 1u);
        }
        __syncthreads();
        if (t < 32) {
            unsigned part = 0;
#pragma unroll
            for (int i = 0; i < 8; i++) part += hist[t*8 + i];
            unsigned cum = part;
#pragma unroll
            for (int o = 1; o < 32; o <<= 1) {
                unsigned v = __shfl_up_sync(0xffffffffu, cum, o);
                if (lane >= o) cum += v;
            }
            unsigned cb = cum - part;
            bool has = (cb < (unsigned)r) && ((unsigned)r <= cum);
            unsigned mball = __ballot_sync(0xffffffffu, has);
            if (t == __ffs(mball) - 1) {
                int rr = r - (int)cb;
                int bb = t*8;
                for (;;) {
                    unsigned h = hist[bb];
                    if (rr <= (int)h) { s_cnt = (int)h; break; }
                    rr -= (int)h; bb++;
                }
                s_bin = bb; s_r = rr;
            }
        }
        __syncthreads();
        prefix |= ((unsigned long long)(unsigned)s_bin) << shift;
        pmask  |= (255ull << shift);
        r = s_r;
        int cnt = s_cnt;
        __syncthreads();
        if (cnt == 1) break;
    }

#pragma unroll 8
    for (int i = 0; i < 32; i++) {
        unsigned long long k = ((unsigned long long)mk[i] << 32) | (unsigned)(t + 128*i);
        if ((k & pmask) == prefix) s_K = k;
    }
    if (t == 0) s_pos = 0;
    __syncthreads();
    const unsigned long long K64 = s_K;

#pragma unroll 8
    for (int i = 0; i < 32; i++) {
        unsigned long long k = ((unsigned long long)mk[i] << 32) | (unsigned)(t + 128*i);
        if (k <= K64) {
            int pos = atomicAdd(&s_pos, 1);
            arr[pos] = k;
        }
    }
    __syncthreads();

    for (int k2 = 2; k2 <= 64; k2 <<= 1)
        for (int j = k2 >> 1; j > 0; j >>= 1) {
            if (t < 64) {
                int ixj = t ^ j;
                if (ixj > t) {
                    unsigned long long a = arr[t], c = arr[ixj];
                    bool up = ((t & k2) == 0);
                    if ((a > c) == up) { arr[t] = c; arr[ixj] = a; }
                }
            }
            __syncthreads();
        }

    if (t < 64) g_knn[q*KMAX + t] = (int)(arr[t] & 0xffffffffu);
}

/* ================== WMMA bf16 (hi/lo split) conv kernels ================= */
/* 128-row tiles, 256 threads; two-pass fused-B K loops (R13 proven)        */
#define LD1 88
#define LD2 72

/* ---- conv1: gather+concat + 80->64 --------------------------------------*/
__global__ void __launch_bounds__(256, 2) conv1_mma(const float* __restrict__ xyz,
                                                    const float* __restrict__ feat,
                                                    const float* __restrict__ W,
                                                    int lgk, int s, unsigned boff)
{
    extern __shared__ char dyn[];
    __nv_bfloat16* Ah = (__nv_bfloat16*)dyn;          /* [128][LD1] */
    __nv_bfloat16* Al = Ah + 128*LD1;
    __nv_bfloat16* Bh = Al + 128*LD1;                 /* [64][LD1]  */
    __nv_bfloat16* Bl = Bh + 64*LD1;
    float* Cs = (float*)dyn;                          /* reuse: [128][64] */
    __shared__ float ps[4][64], pq[4][64];

    const int t = threadIdx.x, tile = blockIdx.x;
    const int wid = t >> 5;

    {
        const int r = t >> 1, sub = t & 1;
        const int gr = tile*128 + r;
        const int q  = gr >> lgk;
        const int j  = gr & ((1 << lgk) - 1);
        const int n  = g_knn[q*KMAX + j];
        const int b  = q >> 10;
        const float* fp = feat + (size_t)(b*NN + n)*CF;
        unsigned* ah = (unsigned*)(Ah + r*LD1);
        unsigned* al = (unsigned*)(Al + r*LD1);
#pragma unroll
        for (int jj = sub*8; jj < sub*8 + 8; jj++) {
            float4 v = *(const float4*)(fp + jj*4);
            unsigned h0, l0, h1, l1;
            split2(v.x, v.y, h0, l0); split2(v.z, v.w, h1, l1);
            ah[jj*2]   = h0; ah[jj*2+1] = h1;
            al[jj*2]   = l0; al[jj*2+1] = l1;
        }
        if (sub) {
            const float* xp = xyz + (size_t)(b*NN + n)*3;
            float dx = xp[0]-g_newxyz[q*3+0], dy = xp[1]-g_newxyz[q*3+1], dz = xp[2]-g_newxyz[q*3+2];
            unsigned h0, l0, h1, l1;
            split2(dx, dy, h0, l0); split2(dz, 0.f, h1, l1);
            ah[32] = h0; ah[33] = h1; al[32] = l0; al[33] = l1;
#pragma unroll
            for (int z = 34; z < 40; z++) { ah[z] = 0u; al[z] = 0u; }
        }
    }
    if (t < 128) {
        const int n = t >> 1, sub = t & 1;
        const float* w = W + n*CIN;
        unsigned* bh = (unsigned*)(Bh + n*LD1);
        unsigned* bl = (unsigned*)(Bl + n*LD1);
#pragma unroll
        for (int jj = sub*16; jj < sub*16 + 16; jj++) {
            unsigned h, l;
            split2(w[3 + jj*2], w[3 + jj*2 + 1], h, l);
            bh[jj] = h; bl[jj] = l;
        }
        if (sub) {
            unsigned h0, l0, h1, l1;
            split2(w[0], w[1], h0, l0); split2(w[2], 0.f, h1, l1);
            bh[32] = h0; bh[33] = h1; bl[32] = l0; bl[33] = l1;
#pragma unroll
            for (int z = 34; z < 40; z++) { bh[z] = 0u; bl[z] = 0u; }
        }
    }
    __syncthreads();

    const int rowg = wid >> 1, colg = wid & 1;
    wmma::fragment<wmma::accumulator, 16, 16, 16, float> acc[2][2];
#pragma unroll
    for (int i = 0; i < 2; i++)
#pragma unroll
        for (int j = 0; j < 2; j++) wmma::fill_fragment(acc[i][j], 0.f);

    /* pass A: (Ah + Al) x Bh */
#pragma unroll
    for (int ks = 0; ks < 5; ks++) {
        wmma::fragment<wmma::matrix_a, 16, 16, 16, __nv_bfloat16, wmma::row_major> afh[2], afl[2];
        wmma::fragment<wmma::matrix_b, 16, 16, 16, __nv_bfloat16, wmma::col_major> bfh[2];
#pragma unroll
        for (int i = 0; i < 2; i++) {
            wmma::load_matrix_sync(afh[i], Ah + (rowg*32 + i*16)*LD1 + ks*16, LD1);
            wmma::load_matrix_sync(afl[i], Al + (rowg*32 + i*16)*LD1 + ks*16, LD1);
        }
#pragma unroll
        for (int j = 0; j < 2; j++)
            wmma::load_matrix_sync(bfh[j], Bh + (colg*32 + j*16)*LD1 + ks*16, LD1);
#pragma unroll
        for (int i = 0; i < 2; i++)
#pragma unroll
            for (int j = 0; j < 2; j++) {
                wmma::mma_sync(acc[i][j], afh[i], bfh[j], acc[i][j]);
                wmma::mma_sync(acc[i][j], afl[i], bfh[j], acc[i][j]);
            }
    }
    /* pass B: Ah x Bl */
#pragma unroll
    for (int ks = 0; ks < 5; ks++) {
        wmma::fragment<wmma::matrix_a, 16, 16, 16, __nv_bfloat16, wmma::row_major> af[2];
        wmma::fragment<wmma::matrix_b, 16, 16, 16, __nv_bfloat16, wmma::col_major> bf[2];
#pragma unroll
        for (int i = 0; i < 2; i++)
            wmma::load_matrix_sync(af[i], Ah + (rowg*32 + i*16)*LD1 + ks*16, LD1);
#pragma unroll
        for (int j = 0; j < 2; j++)
            wmma::load_matrix_sync(bf[j], Bl + (colg*32 + j*16)*LD1 + ks*16, LD1);
#pragma unroll
        for (int i = 0; i < 2; i++)
#pragma unroll
            for (int j = 0; j < 2; j++)
                wmma::mma_sync(acc[i][j], af[i], bf[j], acc[i][j]);
    }
    __syncthreads();
#pragma unroll
    for (int i = 0; i < 2; i++)
#pragma unroll
        for (int j = 0; j < 2; j++)
            wmma::store_matrix_sync(Cs + (rowg*32 + i*16)*64 + colg*32 + j*16,
                                    acc[i][j], 64, wmma::mem_row_major);
    __syncthreads();

    float* bufOut = g_buf1 + boff;
    const size_t base = (size_t)tile*128*64;
    for (int i = t*4; i < 128*64; i += 1024)
        *(float4*)(bufOut + base + i) = *(const float4*)(Cs + i);

    {
        const int c = t & 63, rq = t >> 6;
        float sv = 0.f, q2 = 0.f;
#pragma unroll 8
        for (int r0 = 0; r0 < 32; r0++) {
            float v = Cs[(rq*32 + r0)*64 + c];
            sv += v; q2 = fmaf(v, v, q2);
        }
        ps[rq][c] = sv; pq[rq][c] = q2;
    }
    __syncthreads();
    if (t < 64) {
        atomicAdd(&g_sum[s][0][t], (double)(ps[0][t]+ps[1][t]+ps[2][t]+ps[3][t]));
        atomicAdd(&g_sq[s][0][t],  (double)(pq[0][t]+pq[1][t]+pq[2][t]+pq[3][t]));
    }
}

/* ---- conv2: BN+ReLU load + 64->64 ---------------------------------------*/
__global__ void __launch_bounds__(256, 2) conv2_mma(const float* __restrict__ W,
                                                    const float* __restrict__ gamma,
                                                    const float* __restrict__ beta,
                                                    double invn, int s, unsigned boff)
{
    extern __shared__ char dyn[];
    __nv_bfloat16* Ah = (__nv_bfloat16*)dyn;
    __nv_bfloat16* Al = Ah + 128*LD2;
    __nv_bfloat16* Bh = Al + 128*LD2;
    __nv_bfloat16* Bl = Bh + 64*LD2;
    float* Cs = (float*)dyn;
    __shared__ float sc[64], sh[64], ps[4][64], pq[4][64];

    const int t = threadIdx.x, tile = blockIdx.x;
    const int wid = t >> 5;

    if (t < 64) bn_coeff(s, 0, t, invn, gamma, beta, sc[t], sh[t]);
    __syncthreads();

    {
        const int r = t >> 1, sub = t & 1;
        const float* ip = g_buf1 + boff + ((size_t)tile*128 + r)*64;
        unsigned* ah = (unsigned*)(Ah + r*LD2);
        unsigned* al = (unsigned*)(Al + r*LD2);
#pragma unroll
        for (int jj = sub*8; jj < sub*8 + 8; jj++) {
            float4 v = *(const float4*)(ip + jj*4);
            int c0 = jj*4;
            float a = fmaxf(fmaf(v.x, sc[c0+0], sh[c0+0]), 0.f);
            float b = fmaxf(fmaf(v.y, sc[c0+1], sh[c0+1]), 0.f);
            float c = fmaxf(fmaf(v.z, sc[c0+2], sh[c0+2]), 0.f);
            float d = fmaxf(fmaf(v.w, sc[c0+3], sh[c0+3]), 0.f);
            unsigned h0, l0, h1, l1;
            split2(a, b, h0, l0); split2(c, d, h1, l1);
            ah[jj*2] = h0; ah[jj*2+1] = h1;
            al[jj*2] = l0; al[jj*2+1] = l1;
        }
    }
    if (t < 128) {
        const int n = t >> 1, sub = t & 1;
        const float* w = W + n*64;
        unsigned* bh = (unsigned*)(Bh + n*LD2);
        unsigned* bl = (unsigned*)(Bl + n*LD2);
#pragma unroll
        for (int jj = sub*8; jj < sub*8 + 8; jj++) {
            float4 v = *(const float4*)(w + jj*4);
            unsigned h0, l0, h1, l1;
            split2(v.x, v.y, h0, l0); split2(v.z, v.w, h1, l1);
            bh[jj*2] = h0; bh[jj*2+1] = h1;
            bl[jj*2] = l0; bl[jj*2+1] = l1;
        }
    }
    __syncthreads();

    const int rowg = wid >> 1, colg = wid & 1;
    wmma::fragment<wmma::accumulator, 16, 16, 16, float> acc[2][2];
#pragma unroll
    for (int i = 0; i < 2; i++)
#pragma unroll
        for (int j = 0; j < 2; j++) wmma::fill_fragment(acc[i][j], 0.f);

#pragma unroll
    for (int ks = 0; ks < 4; ks++) {
        wmma::fragment<wmma::matrix_a, 16, 16, 16, __nv_bfloat16, wmma::row_major> afh[2], afl[2];
        wmma::fragment<wmma::matrix_b, 16, 16, 16, __nv_bfloat16, wmma::col_major> bfh[2];
#pragma unroll
        for (int i = 0; i < 2; i++) {
            wmma::load_matrix_sync(afh[i], Ah + (rowg*32 + i*16)*LD2 + ks*16, LD2);
            wmma::load_matrix_sync(afl[i], Al + (rowg*32 + i*16)*LD2 + ks*16, LD2);
        }
#pragma unroll
        for (int j = 0; j < 2; j++)
            wmma::load_matrix_sync(bfh[j], Bh + (colg*32 + j*16)*LD2 + ks*16, LD2);
#pragma unroll
        for (int i = 0; i < 2; i++)
#pragma unroll
            for (int j = 0; j < 2; j++) {
                wmma::mma_sync(acc[i][j], afh[i], bfh[j], acc[i][j]);
                wmma::mma_sync(acc[i][j], afl[i], bfh[j], acc[i][j]);
            }
    }
#pragma unroll
    for (int ks = 0; ks < 4; ks++) {
        wmma::fragment<wmma::matrix_a, 16, 16, 16, __nv_bfloat16, wmma::row_major> af[2];
        wmma::fragment<wmma::matrix_b, 16, 16, 16, __nv_bfloat16, wmma::col_major> bf[2];
#pragma unroll
        for (int i = 0; i < 2; i++)
            wmma::load_matrix_sync(af[i], Ah + (rowg*32 + i*16)*LD2 + ks*16, LD2);
#pragma unroll
        for (int j = 0; j < 2; j++)
            wmma::load_matrix_sync(bf[j], Bl + (colg*32 + j*16)*LD2 + ks*16, LD2);
#pragma unroll
        for (int i = 0; i < 2; i++)
#pragma unroll
            for (int j = 0; j < 2; j++)
                wmma::mma_sync(acc[i][j], af[i], bf[j], acc[i][j]);
    }
    __syncthreads();
#pragma unroll
    for (int i = 0; i < 2; i++)
#pragma unroll
        for (int j = 0; j < 2; j++)
            wmma::store_matrix_sync(Cs + (rowg*32 + i*16)*64 + colg*32 + j*16,
                                    acc[i][j], 64, wmma::mem_row_major);
    __syncthreads();

    float* bufOut = g_buf2 + boff;
    const size_t base = (size_t)tile*128*64;
    for (int i = t*4; i < 128*64; i += 1024)
        *(float4*)(bufOut + base + i) = *(const float4*)(Cs + i);

    {
        const int c = t & 63, rq = t >> 6;
        float sv = 0.f, q2 = 0.f;
#pragma unroll 8
        for (int r0 = 0; r0 < 32; r0++) {
            float v = Cs[(rq*32 + r0)*64 + c];
            sv += v; q2 = fmaf(v, v, q2);
        }
        ps[rq][c] = sv; pq[rq][c] = q2;
    }
    __syncthreads();
    if (t < 64) {
        atomicAdd(&g_sum[s][1][t], (double)(ps[0][t]+ps[1][t]+ps[2][t]+ps[3][t]));
        atomicAdd(&g_sq[s][1][t],  (double)(pq[0][t]+pq[1][t]+pq[2][t]+pq[3][t]));
    }
}

/* ---- conv3: BN+ReLU load + 64->128 + per-query max/min ------------------ */
template<int K>
__global__ void __launch_bounds__(256, 2) conv3_mma(const float* __restrict__ W,
                                                    const float* __restrict__ gamma,
                                                    const float* __restrict__ beta,
                                                    double invn, int s, unsigned boff)
{
    extern __shared__ char dyn[];
    __nv_bfloat16* Ah = (__nv_bfloat16*)dyn;
    __nv_bfloat16* Al = Ah + 128*LD2;
    __nv_bfloat16* Bh = Al + 128*LD2;
    __nv_bfloat16* Bl = Bh + 128*LD2;
    float* Cs = (float*)dyn;                          /* [128][128] */
    __shared__ float sc[64], sh[64], ps[2][128], pq[2][128];

    const int t = threadIdx.x, tile = blockIdx.x;
    const int wid = t >> 5;

    if (t < 64) bn_coeff(s, 1, t, invn, gamma, beta, sc[t], sh[t]);
    __syncthreads();

    {
        const int r = t >> 1, sub = t & 1;
        const float* ip = g_buf2 + boff + ((size_t)tile*128 + r)*64;
        unsigned* ah = (unsigned*)(Ah + r*LD2);
        unsigned* al = (unsigned*)(Al + r*LD2);
#pragma unroll
        for (int jj = sub*8; jj < sub*8 + 8; jj++) {
            float4 v = *(const float4*)(ip + jj*4);
            int c0 = jj*4;
            float a = fmaxf(fmaf(v.x, sc[c0+0], sh[c0+0]), 0.f);
            float b = fmaxf(fmaf(v.y, sc[c0+1], sh[c0+1]), 0.f);
            float c = fmaxf(fmaf(v.z, sc[c0+2], sh[c0+2]), 0.f);
            float d = fmaxf(fmaf(v.w, sc[c0+3], sh[c0+3]), 0.f);
            unsigned h0, l0, h1, l1;
            split2(a, b, h0, l0); split2(c, d, h1, l1);
            ah[jj*2] = h0; ah[jj*2+1] = h1;
            al[jj*2] = l0; al[jj*2+1] = l1;
        }
    }
    {
        const int n = t >> 1, sub = t & 1;
        const float* w = W + (size_t)n*64;
        unsigned* bh = (unsigned*)(Bh + n*LD2);
        unsigned* bl = (unsigned*)(Bl + n*LD2);
#pragma unroll
        for (int jj = sub*8; jj < sub*8 + 8; jj++) {
            float4 v = *(const float4*)(w + jj*4);
            unsigned h0, l0, h1, l1;
            split2(v.x, v.y, h0, l0); split2(v.z, v.w, h1, l1);
            bh[jj*2] = h0; bh[jj*2+1] = h1;
            bl[jj*2] = l0; bl[jj*2+1] = l1;
        }
    }
    __syncthreads();

    const int rowg = wid >> 1, colg = wid & 1;
    wmma::fragment<wmma::accumulator, 16, 16, 16, float> acc[2][4];
#pragma unroll
    for (int i = 0; i < 2; i++)
#pragma unroll
        for (int j = 0; j < 4; j++) wmma::fill_fragment(acc[i][j], 0.f);

    /* pass A: (Ah + Al) x Bh */
#pragma unroll
    for (int ks = 0; ks < 4; ks++) {
        wmma::fragment<wmma::matrix_a, 16, 16, 16, __nv_bfloat16, wmma::row_major> afh[2], afl[2];
#pragma unroll
        for (int i = 0; i < 2; i++) {
            wmma::load_matrix_sync(afh[i], Ah + (rowg*32 + i*16)*LD2 + ks*16, LD2);
            wmma::load_matrix_sync(afl[i], Al + (rowg*32 + i*16)*LD2 + ks*16, LD2);
        }
#pragma unroll
        for (int j = 0; j < 4; j++) {
            wmma::fragment<wmma::matrix_b, 16, 16, 16, __nv_bfloat16, wmma::col_major> bf;
            wmma::load_matrix_sync(bf, Bh + (colg*64 + j*16)*LD2 + ks*16, LD2);
#pragma unroll
            for (int i = 0; i < 2; i++) {
                wmma::mma_sync(acc[i][j], afh[i], bf, acc[i][j]);
                wmma::mma_sync(acc[i][j], afl[i], bf, acc[i][j]);
            }
        }
    }
    /* pass B: Ah x Bl */
#pragma unroll
    for (int ks = 0; ks < 4; ks++) {
        wmma::fragment<wmma::matrix_a, 16, 16, 16, __nv_bfloat16, wmma::row_major> af[2];
#pragma unroll
        for (int i = 0; i < 2; i++)
            wmma::load_matrix_sync(af[i], Ah + (rowg*32 + i*16)*LD2 + ks*16, LD2);
#pragma unroll
        for (int j = 0; j < 4; j++) {
            wmma::fragment<wmma::matrix_b, 16, 16, 16, __nv_bfloat16, wmma::col_major> bf;
            wmma::load_matrix_sync(bf, Bl + (colg*64 + j*16)*LD2 + ks*16, LD2);
#pragma unroll
            for (int i = 0; i < 2; i++)
                wmma::mma_sync(acc[i][j], af[i], bf, acc[i][j]);
        }
    }
    __syncthreads();
#pragma unroll
    for (int i = 0; i < 2; i++)
#pragma unroll
        for (int j = 0; j < 4; j++)
            wmma::store_matrix_sync(Cs + (rowg*32 + i*16)*128 + colg*64 + j*16,
                                    acc[i][j], 128, wmma::mem_row_major);
    __syncthreads();

    {
        const int c = t & 127, rh = t >> 7;
        float sv = 0.f, q2 = 0.f;
#pragma unroll 8
        for (int r0 = 0; r0 < 64; r0++) {
            float v = Cs[(rh*64 + r0)*128 + c];
            sv += v; q2 = fmaf(v, v, q2);
        }
        ps[rh][c] = sv; pq[rh][c] = q2;
    }
    {
        const int c = t & 127, g = t >> 7;
        const int nq_tile = 128 / K;
        float* gmax = g_max + (size_t)s*NQ*128;
        float* gmin = g_min + (size_t)s*NQ*128;
        for (int qi = g; qi < nq_tile; qi += 2) {
            float mx = -3.4e38f, mn = 3.4e38f;
#pragma unroll 8
            for (int r0 = 0; r0 < K; r0++) {
                float v = Cs[(qi*K + r0)*128 + c];
                mx = fmaxf(mx, v); mn = fminf(mn, v);
            }
            const int q = tile*nq_tile + qi;
            gmax[q*128 + c] = mx;
            gmin[q*128 + c] = mn;
        }
    }
    __syncthreads();
    if (t < 128) {
        atomicAdd(&g_sum[s][2][t], (double)(ps[0][t] + ps[1][t]));
        atomicAdd(&g_sq[s][2][t],  (double)(pq[0][t] + pq[1][t]));
    }
}

/* -------- finalize: BN(+sign-aware max/min) + ReLU -> out ---------------- */
__global__ void __launch_bounds__(128) finalize_kernel(float* __restrict__ out,
                                                       const float* __restrict__ gamma,
                                                       const float* __restrict__ beta,
                                                       double invn, int s)
{
    const int q = blockIdx.x;
    const int c = threadIdx.x;
    float scl, shf;
    bn_coeff(s, 2, c, invn, gamma, beta, scl, shf);
    const float* gmax = g_max + (size_t)s*NQ*128;
    const float* gmin = g_min + (size_t)s*NQ*128;
    float sel = (scl >= 0.f) ? gmax[q*128 + c] : gmin[q*128 + c];
    out[(size_t)NQ*3 + (size_t)q*384 + s*128 + c] = fmaxf(fmaf(sel, scl, shf), 0.f);
}

/* ------------------------------ driver ----------------------------------- */
extern "C" void kernel_launch(void* const* d_in, const int* in_sizes, int n_in,
                              void* d_out, int out_size)
{
    const float* xyz  = (const float*)d_in[0];
    const float* feat = (const float*)d_in[1];
    const float* w0   = (const float*)d_in[2];
    const float* w1   = (const float*)d_in[3];
    const float* w2   = (const float*)d_in[4];
    const float* g0   = (const float*)d_in[5];
    const float* g1   = (const float*)d_in[6];
    const float* g2   = (const float*)d_in[7];
    const float* b0   = (const float*)d_in[8];
    const float* b1   = (const float*)d_in[9];
    const float* b2   = (const float*)d_in[10];
    float* out = (float*)d_out;

    const int SM1 = (2*128*LD1 + 2*64*LD1) * 2;     /* 67584 */
    const int SM2 = (2*128*LD2 + 2*64*LD2) * 2;     /* 55296 */
    const int SM3 = (2*128*LD2 + 2*128*LD2) * 2;    /* 73728 */
    cudaFuncSetAttribute(conv1_mma, cudaFuncAttributeMaxDynamicSharedMemorySize, SM1);
    cudaFuncSetAttribute(conv2_mma, cudaFuncAttributeMaxDynamicSharedMemorySize, SM2);
    cudaFuncSetAttribute(conv3_mma<16>, cudaFuncAttributeMaxDynamicSharedMemorySize, SM3);
    cudaFuncSetAttribute(conv3_mma<32>, cudaFuncAttributeMaxDynamicSharedMemorySize, SM3);
    cudaFuncSetAttribute(conv3_mma<64>, cudaFuncAttributeMaxDynamicSharedMemorySize, SM3);

    init_kernel<<<1, 128>>>();
    fps_kernel<<<BB, 1024>>>(xyz, out);
    knn_kernel<<<NQ, 128>>>(xyz);

    const int      KS[3]  = {16, 32, 64};
    const int      LGK[3] = {4, 5, 6};
    const unsigned OFF[3] = {B1OFF0, B1OFF1, B1OFF2};

    for (int s = 0; s < 3; s++) {
        const int k = KS[s];
        const int R = NQ * k;
        const double invn = 1.0 / (double)R;

        conv1_mma<<<R/128, 256, SM1>>>(xyz, feat, w0 + (size_t)s*64*CIN, LGK[s], s, OFF[s]);
        conv2_mma<<<R/128, 256, SM2>>>(w1 + (size_t)s*64*64, g0 + s*64, b0 + s*64,
                                       invn, s, OFF[s]);
        if (k == 16)
            conv3_mma<16><<<R/128, 256, SM3>>>(w2 + (size_t)s*128*64, g1 + s*64, b1 + s*64,
                                               invn, s, OFF[s]);
        else if (k == 32)
            conv3_mma<32><<<R/128, 256, SM3>>>(w2 + (size_t)s*128*64, g1 + s*64, b1 + s*64,
                                               invn, s, OFF[s]);
        else
            conv3_mma<64><<<R/128, 256, SM3>>>(w2 + (size_t)s*128*64, g1 + s*64, b1 + s*64,
                                               invn, s, OFF[s]);
        finalize_kernel<<<NQ, 128>>>(out, g2 + s*128, b2 + s*128, invn, s);
    }
}

// round 16
// speedup vs baseline: 1.0343x; 1.0080x over previous
#include <cuda_runtime.h>
#include <cuda_bf16.h>
#include <mma.h>
#include <cstdint>

using namespace nvcuda;

#define BB 16
#define NN 4096
#define SS 1024
#define NQ (BB*SS)
#define KMAX 64
#define CIN 67
#define CF  64

/* ---------------- scratch (device globals; no allocation allowed) -------- */
__device__ int    g_knn[NQ*KMAX];
__device__ float  g_newxyz[NQ*3];
#define B1OFF0 0u
#define B1OFF1 (16384u*16u*64u)
#define B1OFF2 (B1OFF1 + 16384u*32u*64u)
#define B1TOT  (B1OFF2 + 16384u*64u*64u)
__device__ float  g_buf1[B1TOT];
__device__ float  g_buf2[B1TOT];
__device__ float  g_max[(size_t)3*NQ*128];
__device__ float  g_min[(size_t)3*NQ*128];
__device__ double g_sum[3][3][128];   /* [scale][layer][chan] */
__device__ double g_sq[3][3][128];

/* block -> (s, tile) decode for fused per-layer launches:
   segment sizes 2048 / 4096 / 8192 */
__device__ __forceinline__ void decode_scale(int bid, int &s, int &tile)
{
    if (bid < 2048)      { s = 0; tile = bid; }
    else if (bid < 6144) { s = 1; tile = bid - 2048; }
    else                 { s = 2; tile = bid - 6144; }
}
__device__ __forceinline__ unsigned scale_boff(int s)
{
    return (s == 0) ? B1OFF0 : (s == 1) ? B1OFF1 : B1OFF2;
}

/* split a,b (fp32) into packed bf16 hi-pair and lo-pair (a in low 16 bits) */
__device__ __forceinline__ void split2(float a, float b, unsigned &hi, unsigned &lo)
{
    __nv_bfloat16 ah = __float2bfloat16(a), bh = __float2bfloat16(b);
    float ar = a - __bfloat162float(ah), br = b - __bfloat162float(bh);
    __nv_bfloat16 al = __float2bfloat16(ar), bl = __float2bfloat16(br);
    hi = (unsigned)__bfloat16_as_ushort(ah) | ((unsigned)__bfloat16_as_ushort(bh) << 16);
    lo = (unsigned)__bfloat16_as_ushort(al) | ((unsigned)__bfloat16_as_ushort(bl) << 16);
}

/* BN scale/shift from raw sums — identical math to the old stats_kernel */
__device__ __forceinline__ void bn_coeff(int s, int layer, int c, double invn,
                                         const float* gamma, const float* beta,
                                         float &scl, float &shf)
{
    double sv = g_sum[s][layer][c], q2 = g_sq[s][layer][c];
    double mu = sv * invn;
    double var = q2 * invn - mu * mu;
    float rstd = rsqrtf((float)var + 1e-5f);
    scl = gamma[c] * rstd;
    shf = beta[c] - (float)mu * scl;
}

/* --------------------------- init ---------------------------------------- */
__global__ void init_kernel()
{
    int t = threadIdx.x;
    if (t < 128) {
#pragma unroll
        for (int s = 0; s < 3; s++)
#pragma unroll
            for (int l = 0; l < 3; l++) {
                g_sum[s][l][t] = 0.0;
                g_sq[s][l][t]  = 0.0;
            }
    }
}

/* ------------------------------- FPS (single barrier/iter) --------------- */
__global__ void __launch_bounds__(1024) fps_kernel(const float* __restrict__ xyz,
                                                   float* __restrict__ out_newxyz)
{
    const int b = blockIdx.x;
    const int t = threadIdx.x;
    const int lane = t & 31, wid = t >> 5;
    const float* X = xyz + (size_t)b*NN*3;

    float px[4], py[4], pz[4], dd[4];
#pragma unroll
    for (int j = 0; j < 4; j++) {
        int p = t + 1024*j;
        px[j] = X[p*3+0]; py[j] = X[p*3+1]; pz[j] = X[p*3+2];
        dd[j] = 1e10f;
    }
    __shared__ unsigned long long wb[2][32];
    int far = 0;

    for (int it = 0; it < SS; ++it) {
        const int par = it & 1;
        float cx = X[far*3+0], cy = X[far*3+1], cz = X[far*3+2];
        if (t == 0) {
            int o = b*SS + it;
            out_newxyz[o*3+0] = cx; out_newxyz[o*3+1] = cy; out_newxyz[o*3+2] = cz;
            g_newxyz[o*3+0]  = cx; g_newxyz[o*3+1]  = cy; g_newxyz[o*3+2]  = cz;
        }
        unsigned long long best = 0ull;
#pragma unroll
        for (int j = 0; j < 4; j++) {
            float dx = px[j]-cx, dy = py[j]-cy, dz = pz[j]-cz;
            float d  = fmaf(dz, dz, fmaf(dy, dy, dx*dx));
            dd[j] = fminf(dd[j], d);
            int p = t + 1024*j;
            unsigned long long key =
                (((unsigned long long)__float_as_uint(dd[j])) << 32) | (unsigned)(NN-1-p);
            best = (key > best) ? key : best;
        }
#pragma unroll
        for (int o = 16; o; o >>= 1) {
            unsigned long long v = __shfl_xor_sync(0xffffffffu, best, o);
            if (v > best) best = v;
        }
        if (lane == 0) wb[par][wid] = best;
        __syncthreads();
        unsigned long long v = wb[par][lane];
#pragma unroll
        for (int o = 16; o; o >>= 1) {
            unsigned long long u = __shfl_xor_sync(0xffffffffu, v, o);
            if (u > v) v = u;
        }
        far = NN - 1 - (int)(v & 0xffffffffu);
    }
}

/* ------------------- kNN: O(N) radix-select + bitonic -------------------- */
__device__ __forceinline__ unsigned mono_f32(float v)
{
    unsigned u = __float_as_uint(v);
    return (u & 0x80000000u) ? ~u : (u | 0x80000000u);
}

__global__ void __launch_bounds__(128) knn_kernel(const float* __restrict__ xyz)
{
    const int q = blockIdx.x;
    const int b = q >> 10;
    const int t = threadIdx.x;
    const int lane = t & 31;
    __shared__ unsigned hist[256];
    __shared__ unsigned long long arr[64];
    __shared__ unsigned long long s_K;
    __shared__ int s_bin, s_r, s_cnt, s_pos;
    const float* X = xyz + (size_t)b*NN*3;

    const float qx = g_newxyz[q*3+0], qy = g_newxyz[q*3+1], qz = g_newxyz[q*3+2];
    const float qq = qx*qx + qy*qy + qz*qz;

    unsigned mk[32];
#pragma unroll 8
    for (int i = 0; i < 32; i++) {
        int p = t + 128*i;
        float x = X[p*3+0], y = X[p*3+1], z = X[p*3+2];
        float pp  = x*x + y*y + z*z;
        float dot = qx*x + qy*y + qz*z;
        float d2  = qq + pp - 2.0f*dot;
        mk[i] = mono_f32(d2);
    }

    unsigned long long prefix = 0ull, pmask = 0ull;
    int r = KMAX;
    for (int shift = 56; shift >= 0; shift -= 8) {
        hist[t] = 0u; hist[t+128] = 0u;
        __syncthreads();
#pragma unroll 8
        for (int i = 0; i < 32; i++) {
            unsigned long long k = ((unsigned long long)mk[i] << 32) | (unsigned)(t + 128*i);
            if ((k & pmask) == prefix)
                atomicAdd(&hist[(unsigned)(k >> shift) & 255u], 1u);
        }
        __syncthreads();
        if (t < 32) {
            unsigned part = 0;
#pragma unroll
            for (int i = 0; i < 8; i++) part += hist[t*8 + i];
            unsigned cum = part;
#pragma unroll
            for (int o = 1; o < 32; o <<= 1) {
                unsigned v = __shfl_up_sync(0xffffffffu, cum, o);
                if (lane >= o) cum += v;
            }
            unsigned cb = cum - part;
            bool has = (cb < (unsigned)r) && ((unsigned)r <= cum);
            unsigned mball = __ballot_sync(0xffffffffu, has);
            if (t == __ffs(mball) - 1) {
                int rr = r - (int)cb;
                int bb = t*8;
                for (;;) {
                    unsigned h = hist[bb];
                    if (rr <= (int)h) { s_cnt = (int)h; break; }
                    rr -= (int)h; bb++;
                }
                s_bin = bb; s_r = rr;
            }
        }
        __syncthreads();
        prefix |= ((unsigned long long)(unsigned)s_bin) << shift;
        pmask  |= (255ull << shift);
        r = s_r;
        int cnt = s_cnt;
        __syncthreads();
        if (cnt == 1) break;
    }

#pragma unroll 8
    for (int i = 0; i < 32; i++) {
        unsigned long long k = ((unsigned long long)mk[i] << 32) | (unsigned)(t + 128*i);
        if ((k & pmask) == prefix) s_K = k;
    }
    if (t == 0) s_pos = 0;
    __syncthreads();
    const unsigned long long K64 = s_K;

#pragma unroll 8
    for (int i = 0; i < 32; i++) {
        unsigned long long k = ((unsigned long long)mk[i] << 32) | (unsigned)(t + 128*i);
        if (k <= K64) {
            int pos = atomicAdd(&s_pos, 1);
            arr[pos] = k;
        }
    }
    __syncthreads();

    for (int k2 = 2; k2 <= 64; k2 <<= 1)
        for (int j = k2 >> 1; j > 0; j >>= 1) {
            if (t < 64) {
                int ixj = t ^ j;
                if (ixj > t) {
                    unsigned long long a = arr[t], c = arr[ixj];
                    bool up = ((t & k2) == 0);
                    if ((a > c) == up) { arr[t] = c; arr[ixj] = a; }
                }
            }
            __syncthreads();
        }

    if (t < 64) g_knn[q*KMAX + t] = (int)(arr[t] & 0xffffffffu);
}

/* ================== WMMA bf16 (hi/lo split) conv kernels ================= */
/* 128-row tiles, 256 threads; two-pass fused-B K loops (R13/R15 proven);   */
/* each layer fused across the 3 scales (block segments 2048/4096/8192)     */
#define LD1 88
#define LD2 72

/* ---- conv1: gather+concat + 80->64 --------------------------------------*/
__global__ void __launch_bounds__(256, 2) conv1_mma(const float* __restrict__ xyz,
                                                    const float* __restrict__ feat,
                                                    const float* __restrict__ w0)
{
    extern __shared__ char dyn[];
    __nv_bfloat16* Ah = (__nv_bfloat16*)dyn;          /* [128][LD1] */
    __nv_bfloat16* Al = Ah + 128*LD1;
    __nv_bfloat16* Bh = Al + 128*LD1;                 /* [64][LD1]  */
    __nv_bfloat16* Bl = Bh + 64*LD1;
    float* Cs = (float*)dyn;                          /* reuse: [128][64] */
    __shared__ float ps[4][64], pq[4][64];

    const int t = threadIdx.x;
    int s, tile;
    decode_scale(blockIdx.x, s, tile);
    const int lgk = 4 + s;
    const unsigned boff = scale_boff(s);
    const float* W = w0 + (size_t)s*64*CIN;
    const int wid = t >> 5;

    {
        const int r = t >> 1, sub = t & 1;
        const int gr = tile*128 + r;
        const int q  = gr >> lgk;
        const int j  = gr & ((1 << lgk) - 1);
        const int n  = g_knn[q*KMAX + j];
        const int b  = q >> 10;
        const float* fp = feat + (size_t)(b*NN + n)*CF;
        unsigned* ah = (unsigned*)(Ah + r*LD1);
        unsigned* al = (unsigned*)(Al + r*LD1);
#pragma unroll
        for (int jj = sub*8; jj < sub*8 + 8; jj++) {
            float4 v = *(const float4*)(fp + jj*4);
            unsigned h0, l0, h1, l1;
            split2(v.x, v.y, h0, l0); split2(v.z, v.w, h1, l1);
            ah[jj*2]   = h0; ah[jj*2+1] = h1;
            al[jj*2]   = l0; al[jj*2+1] = l1;
        }
        if (sub) {
            const float* xp = xyz + (size_t)(b*NN + n)*3;
            float dx = xp[0]-g_newxyz[q*3+0], dy = xp[1]-g_newxyz[q*3+1], dz = xp[2]-g_newxyz[q*3+2];
            unsigned h0, l0, h1, l1;
            split2(dx, dy, h0, l0); split2(dz, 0.f, h1, l1);
            ah[32] = h0; ah[33] = h1; al[32] = l0; al[33] = l1;
#pragma unroll
            for (int z = 34; z < 40; z++) { ah[z] = 0u; al[z] = 0u; }
        }
    }
    if (t < 128) {
        const int n = t >> 1, sub = t & 1;
        const float* w = W + n*CIN;
        unsigned* bh = (unsigned*)(Bh + n*LD1);
        unsigned* bl = (unsigned*)(Bl + n*LD1);
#pragma unroll
        for (int jj = sub*16; jj < sub*16 + 16; jj++) {
            unsigned h, l;
            split2(w[3 + jj*2], w[3 + jj*2 + 1], h, l);
            bh[jj] = h; bl[jj] = l;
        }
        if (sub) {
            unsigned h0, l0, h1, l1;
            split2(w[0], w[1], h0, l0); split2(w[2], 0.f, h1, l1);
            bh[32] = h0; bh[33] = h1; bl[32] = l0; bl[33] = l1;
#pragma unroll
            for (int z = 34; z < 40; z++) { bh[z] = 0u; bl[z] = 0u; }
        }
    }
    __syncthreads();

    const int rowg = wid >> 1, colg = wid & 1;
    wmma::fragment<wmma::accumulator, 16, 16, 16, float> acc[2][2];
#pragma unroll
    for (int i = 0; i < 2; i++)
#pragma unroll
        for (int j = 0; j < 2; j++) wmma::fill_fragment(acc[i][j], 0.f);

    /* pass A: (Ah + Al) x Bh */
#pragma unroll
    for (int ks = 0; ks < 5; ks++) {
        wmma::fragment<wmma::matrix_a, 16, 16, 16, __nv_bfloat16, wmma::row_major> afh[2], afl[2];
        wmma::fragment<wmma::matrix_b, 16, 16, 16, __nv_bfloat16, wmma::col_major> bfh[2];
#pragma unroll
        for (int i = 0; i < 2; i++) {
            wmma::load_matrix_sync(afh[i], Ah + (rowg*32 + i*16)*LD1 + ks*16, LD1);
            wmma::load_matrix_sync(afl[i], Al + (rowg*32 + i*16)*LD1 + ks*16, LD1);
        }
#pragma unroll
        for (int j = 0; j < 2; j++)
            wmma::load_matrix_sync(bfh[j], Bh + (colg*32 + j*16)*LD1 + ks*16, LD1);
#pragma unroll
        for (int i = 0; i < 2; i++)
#pragma unroll
            for (int j = 0; j < 2; j++) {
                wmma::mma_sync(acc[i][j], afh[i], bfh[j], acc[i][j]);
                wmma::mma_sync(acc[i][j], afl[i], bfh[j], acc[i][j]);
            }
    }
    /* pass B: Ah x Bl */
#pragma unroll
    for (int ks = 0; ks < 5; ks++) {
        wmma::fragment<wmma::matrix_a, 16, 16, 16, __nv_bfloat16, wmma::row_major> af[2];
        wmma::fragment<wmma::matrix_b, 16, 16, 16, __nv_bfloat16, wmma::col_major> bf[2];
#pragma unroll
        for (int i = 0; i < 2; i++)
            wmma::load_matrix_sync(af[i], Ah + (rowg*32 + i*16)*LD1 + ks*16, LD1);
#pragma unroll
        for (int j = 0; j < 2; j++)
            wmma::load_matrix_sync(bf[j], Bl + (colg*32 + j*16)*LD1 + ks*16, LD1);
#pragma unroll
        for (int i = 0; i < 2; i++)
#pragma unroll
            for (int j = 0; j < 2; j++)
                wmma::mma_sync(acc[i][j], af[i], bf[j], acc[i][j]);
    }
    __syncthreads();
#pragma unroll
    for (int i = 0; i < 2; i++)
#pragma unroll
        for (int j = 0; j < 2; j++)
            wmma::store_matrix_sync(Cs + (rowg*32 + i*16)*64 + colg*32 + j*16,
                                    acc[i][j], 64, wmma::mem_row_major);
    __syncthreads();

    float* bufOut = g_buf1 + boff;
    const size_t base = (size_t)tile*128*64;
    for (int i = t*4; i < 128*64; i += 1024)
        *(float4*)(bufOut + base + i) = *(const float4*)(Cs + i);

    {
        const int c = t & 63, rq = t >> 6;
        float sv = 0.f, q2 = 0.f;
#pragma unroll 8
        for (int r0 = 0; r0 < 32; r0++) {
            float v = Cs[(rq*32 + r0)*64 + c];
            sv += v; q2 = fmaf(v, v, q2);
        }
        ps[rq][c] = sv; pq[rq][c] = q2;
    }
    __syncthreads();
    if (t < 64) {
        atomicAdd(&g_sum[s][0][t], (double)(ps[0][t]+ps[1][t]+ps[2][t]+ps[3][t]));
        atomicAdd(&g_sq[s][0][t],  (double)(pq[0][t]+pq[1][t]+pq[2][t]+pq[3][t]));
    }
}

/* ---- conv2: BN+ReLU load + 64->64 ---------------------------------------*/
__global__ void __launch_bounds__(256, 2) conv2_mma(const float* __restrict__ w1,
                                                    const float* __restrict__ g0,
                                                    const float* __restrict__ b0)
{
    extern __shared__ char dyn[];
    __nv_bfloat16* Ah = (__nv_bfloat16*)dyn;
    __nv_bfloat16* Al = Ah + 128*LD2;
    __nv_bfloat16* Bh = Al + 128*LD2;
    __nv_bfloat16* Bl = Bh + 64*LD2;
    float* Cs = (float*)dyn;
    __shared__ float sc[64], sh[64], ps[4][64], pq[4][64];

    const int t = threadIdx.x;
    int s, tile;
    decode_scale(blockIdx.x, s, tile);
    const unsigned boff = scale_boff(s);
    const float* W = w1 + (size_t)s*64*64;
    const double invn = 1.0 / (double)(NQ * (16 << s));
    const int wid = t >> 5;

    if (t < 64) bn_coeff(s, 0, t, invn, g0 + s*64, b0 + s*64, sc[t], sh[t]);
    __syncthreads();

    {
        const int r = t >> 1, sub = t & 1;
        const float* ip = g_buf1 + boff + ((size_t)tile*128 + r)*64;
        unsigned* ah = (unsigned*)(Ah + r*LD2);
        unsigned* al = (unsigned*)(Al + r*LD2);
#pragma unroll
        for (int jj = sub*8; jj < sub*8 + 8; jj++) {
            float4 v = *(const float4*)(ip + jj*4);
            int c0 = jj*4;
            float a = fmaxf(fmaf(v.x, sc[c0+0], sh[c0+0]), 0.f);
            float b = fmaxf(fmaf(v.y, sc[c0+1], sh[c0+1]), 0.f);
            float c = fmaxf(fmaf(v.z, sc[c0+2], sh[c0+2]), 0.f);
            float d = fmaxf(fmaf(v.w, sc[c0+3], sh[c0+3]), 0.f);
            unsigned h0, l0, h1, l1;
            split2(a, b, h0, l0); split2(c, d, h1, l1);
            ah[jj*2] = h0; ah[jj*2+1] = h1;
            al[jj*2] = l0; al[jj*2+1] = l1;
        }
    }
    if (t < 128) {
        const int n = t >> 1, sub = t & 1;
        const float* w = W + n*64;
        unsigned* bh = (unsigned*)(Bh + n*LD2);
        unsigned* bl = (unsigned*)(Bl + n*LD2);
#pragma unroll
        for (int jj = sub*8; jj < sub*8 + 8; jj++) {
            float4 v = *(const float4*)(w + jj*4);
            unsigned h0, l0, h1, l1;
            split2(v.x, v.y, h0, l0); split2(v.z, v.w, h1, l1);
            bh[jj*2] = h0; bh[jj*2+1] = h1;
            bl[jj*2] = l0; bl[jj*2+1] = l1;
        }
    }
    __syncthreads();

    const int rowg = wid >> 1, colg = wid & 1;
    wmma::fragment<wmma::accumulator, 16, 16, 16, float> acc[2][2];
#pragma unroll
    for (int i = 0; i < 2; i++)
#pragma unroll
        for (int j = 0; j < 2; j++) wmma::fill_fragment(acc[i][j], 0.f);

#pragma unroll
    for (int ks = 0; ks < 4; ks++) {
        wmma::fragment<wmma::matrix_a, 16, 16, 16, __nv_bfloat16, wmma::row_major> afh[2], afl[2];
        wmma::fragment<wmma::matrix_b, 16, 16, 16, __nv_bfloat16, wmma::col_major> bfh[2];
#pragma unroll
        for (int i = 0; i < 2; i++) {
            wmma::load_matrix_sync(afh[i], Ah + (rowg*32 + i*16)*LD2 + ks*16, LD2);
            wmma::load_matrix_sync(afl[i], Al + (rowg*32 + i*16)*LD2 + ks*16, LD2);
        }
#pragma unroll
        for (int j = 0; j < 2; j++)
            wmma::load_matrix_sync(bfh[j], Bh + (colg*32 + j*16)*LD2 + ks*16, LD2);
#pragma unroll
        for (int i = 0; i < 2; i++)
#pragma unroll
            for (int j = 0; j < 2; j++) {
                wmma::mma_sync(acc[i][j], afh[i], bfh[j], acc[i][j]);
                wmma::mma_sync(acc[i][j], afl[i], bfh[j], acc[i][j]);
            }
    }
#pragma unroll
    for (int ks = 0; ks < 4; ks++) {
        wmma::fragment<wmma::matrix_a, 16, 16, 16, __nv_bfloat16, wmma::row_major> af[2];
        wmma::fragment<wmma::matrix_b, 16, 16, 16, __nv_bfloat16, wmma::col_major> bf[2];
#pragma unroll
        for (int i = 0; i < 2; i++)
            wmma::load_matrix_sync(af[i], Ah + (rowg*32 + i*16)*LD2 + ks*16, LD2);
#pragma unroll
        for (int j = 0; j < 2; j++)
            wmma::load_matrix_sync(bf[j], Bl + (colg*32 + j*16)*LD2 + ks*16, LD2);
#pragma unroll
        for (int i = 0; i < 2; i++)
#pragma unroll
            for (int j = 0; j < 2; j++)
                wmma::mma_sync(acc[i][j], af[i], bf[j], acc[i][j]);
    }
    __syncthreads();
#pragma unroll
    for (int i = 0; i < 2; i++)
#pragma unroll
        for (int j = 0; j < 2; j++)
            wmma::store_matrix_sync(Cs + (rowg*32 + i*16)*64 + colg*32 + j*16,
                                    acc[i][j], 64, wmma::mem_row_major);
    __syncthreads();

    float* bufOut = g_buf2 + boff;
    const size_t base = (size_t)tile*128*64;
    for (int i = t*4; i < 128*64; i += 1024)
        *(float4*)(bufOut + base + i) = *(const float4*)(Cs + i);

    {
        const int c = t & 63, rq = t >> 6;
        float sv = 0.f, q2 = 0.f;
#pragma unroll 8
        for (int r0 = 0; r0 < 32; r0++) {
            float v = Cs[(rq*32 + r0)*64 + c];
            sv += v; q2 = fmaf(v, v, q2);
        }
        ps[rq][c] = sv; pq[rq][c] = q2;
    }
    __syncthreads();
    if (t < 64) {
        atomicAdd(&g_sum[s][1][t], (double)(ps[0][t]+ps[1][t]+ps[2][t]+ps[3][t]));
        atomicAdd(&g_sq[s][1][t],  (double)(pq[0][t]+pq[1][t]+pq[2][t]+pq[3][t]));
    }
}

/* ---- conv3: BN+ReLU load + 64->128 + per-query max/min (runtime K) ------ */
__global__ void __launch_bounds__(256, 2) conv3_mma(const float* __restrict__ w2,
                                                    const float* __restrict__ g1,
                                                    const float* __restrict__ b1)
{
    extern __shared__ char dyn[];
    __nv_bfloat16* Ah = (__nv_bfloat16*)dyn;
    __nv_bfloat16* Al = Ah + 128*LD2;
    __nv_bfloat16* Bh = Al + 128*LD2;
    __nv_bfloat16* Bl = Bh + 128*LD2;
    float* Cs = (float*)dyn;                          /* [128][128] */
    __shared__ float sc[64], sh[64], ps[2][128], pq[2][128];

    const int t = threadIdx.x;
    int s, tile;
    decode_scale(blockIdx.x, s, tile);
    const int K = 16 << s;
    const unsigned boff = scale_boff(s);
    const float* W = w2 + (size_t)s*128*64;
    const double invn = 1.0 / (double)(NQ * K);
    const int wid = t >> 5;

    if (t < 64) bn_coeff(s, 1, t, invn, g1 + s*64, b1 + s*64, sc[t], sh[t]);
    __syncthreads();

    {
        const int r = t >> 1, sub = t & 1;
        const float* ip = g_buf2 + boff + ((size_t)tile*128 + r)*64;
        unsigned* ah = (unsigned*)(Ah + r*LD2);
        unsigned* al = (unsigned*)(Al + r*LD2);
#pragma unroll
        for (int jj = sub*8; jj < sub*8 + 8; jj++) {
            float4 v = *(const float4*)(ip + jj*4);
            int c0 = jj*4;
            float a = fmaxf(fmaf(v.x, sc[c0+0], sh[c0+0]), 0.f);
            float b = fmaxf(fmaf(v.y, sc[c0+1], sh[c0+1]), 0.f);
            float c = fmaxf(fmaf(v.z, sc[c0+2], sh[c0+2]), 0.f);
            float d = fmaxf(fmaf(v.w, sc[c0+3], sh[c0+3]), 0.f);
            unsigned h0, l0, h1, l1;
            split2(a, b, h0, l0); split2(c, d, h1, l1);
            ah[jj*2] = h0; ah[jj*2+1] = h1;
            al[jj*2] = l0; al[jj*2+1] = l1;
        }
    }
    {
        const int n = t >> 1, sub = t & 1;
        const float* w = W + (size_t)n*64;
        unsigned* bh = (unsigned*)(Bh + n*LD2);
        unsigned* bl = (unsigned*)(Bl + n*LD2);
#pragma unroll
        for (int jj = sub*8; jj < sub*8 + 8; jj++) {
            float4 v = *(const float4*)(w + jj*4);
            unsigned h0, l0, h1, l1;
            split2(v.x, v.y, h0, l0); split2(v.z, v.w, h1, l1);
            bh[jj*2] = h0; bh[jj*2+1] = h1;
            bl[jj*2] = l0; bl[jj*2+1] = l1;
        }
    }
    __syncthreads();

    const int rowg = wid >> 1, colg = wid & 1;
    wmma::fragment<wmma::accumulator, 16, 16, 16, float> acc[2][4];
#pragma unroll
    for (int i = 0; i < 2; i++)
#pragma unroll
        for (int j = 0; j < 4; j++) wmma::fill_fragment(acc[i][j], 0.f);

    /* pass A: (Ah + Al) x Bh */
#pragma unroll
    for (int ks = 0; ks < 4; ks++) {
        wmma::fragment<wmma::matrix_a, 16, 16, 16, __nv_bfloat16, wmma::row_major> afh[2], afl[2];
#pragma unroll
        for (int i = 0; i < 2; i++) {
            wmma::load_matrix_sync(afh[i], Ah + (rowg*32 + i*16)*LD2 + ks*16, LD2);
            wmma::load_matrix_sync(afl[i], Al + (rowg*32 + i*16)*LD2 + ks*16, LD2);
        }
#pragma unroll
        for (int j = 0; j < 4; j++) {
            wmma::fragment<wmma::matrix_b, 16, 16, 16, __nv_bfloat16, wmma::col_major> bf;
            wmma::load_matrix_sync(bf, Bh + (colg*64 + j*16)*LD2 + ks*16, LD2);
#pragma unroll
            for (int i = 0; i < 2; i++) {
                wmma::mma_sync(acc[i][j], afh[i], bf, acc[i][j]);
                wmma::mma_sync(acc[i][j], afl[i], bf, acc[i][j]);
            }
        }
    }
    /* pass B: Ah x Bl */
#pragma unroll
    for (int ks = 0; ks < 4; ks++) {
        wmma::fragment<wmma::matrix_a, 16, 16, 16, __nv_bfloat16, wmma::row_major> af[2];
#pragma unroll
        for (int i = 0; i < 2; i++)
            wmma::load_matrix_sync(af[i], Ah + (rowg*32 + i*16)*LD2 + ks*16, LD2);
#pragma unroll
        for (int j = 0; j < 4; j++) {
            wmma::fragment<wmma::matrix_b, 16, 16, 16, __nv_bfloat16, wmma::col_major> bf;
            wmma::load_matrix_sync(bf, Bl + (colg*64 + j*16)*LD2 + ks*16, LD2);
#pragma unroll
            for (int i = 0; i < 2; i++)
                wmma::mma_sync(acc[i][j], af[i], bf, acc[i][j]);
        }
    }
    __syncthreads();
#pragma unroll
    for (int i = 0; i < 2; i++)
#pragma unroll
        for (int j = 0; j < 4; j++)
            wmma::store_matrix_sync(Cs + (rowg*32 + i*16)*128 + colg*64 + j*16,
                                    acc[i][j], 128, wmma::mem_row_major);
    __syncthreads();

    {
        const int c = t & 127, rh = t >> 7;
        float sv = 0.f, q2 = 0.f;
#pragma unroll 8
        for (int r0 = 0; r0 < 64; r0++) {
            float v = Cs[(rh*64 + r0)*128 + c];
            sv += v; q2 = fmaf(v, v, q2);
        }
        ps[rh][c] = sv; pq[rh][c] = q2;
    }
    {
        const int c = t & 127, g = t >> 7;
        const int nq_tile = 128 / K;
        float* gmax = g_max + (size_t)s*NQ*128;
        float* gmin = g_min + (size_t)s*NQ*128;
        for (int qi = g; qi < nq_tile; qi += 2) {
            float mx = -3.4e38f, mn = 3.4e38f;
#pragma unroll 8
            for (int r0 = 0; r0 < K; r0++) {
                float v = Cs[(qi*K + r0)*128 + c];
                mx = fmaxf(mx, v); mn = fminf(mn, v);
            }
            const int q = tile*nq_tile + qi;
            gmax[q*128 + c] = mx;
            gmin[q*128 + c] = mn;
        }
    }
    __syncthreads();
    if (t < 128) {
        atomicAdd(&g_sum[s][2][t], (double)(ps[0][t] + ps[1][t]));
        atomicAdd(&g_sq[s][2][t],  (double)(pq[0][t] + pq[1][t]));
    }
}

/* -------- finalize (all scales): BN + sign-aware max/min + ReLU ---------- */
__global__ void __launch_bounds__(384) finalize_kernel(float* __restrict__ out,
                                                       const float* __restrict__ g2,
                                                       const float* __restrict__ b2)
{
    const int q = blockIdx.x;
    const int t = threadIdx.x;
    const int s = t >> 7, c = t & 127;
    const double invn = 1.0 / (double)(NQ * (16 << s));
    float scl, shf;
    bn_coeff(s, 2, c, invn, g2 + s*128, b2 + s*128, scl, shf);
    const float* gmax = g_max + (size_t)s*NQ*128;
    const float* gmin = g_min + (size_t)s*NQ*128;
    float sel = (scl >= 0.f) ? gmax[q*128 + c] : gmin[q*128 + c];
    out[(size_t)NQ*3 + (size_t)q*384 + t] = fmaxf(fmaf(sel, scl, shf), 0.f);
}

/* ------------------------------ driver ----------------------------------- */
extern "C" void kernel_launch(void* const* d_in, const int* in_sizes, int n_in,
                              void* d_out, int out_size)
{
    const float* xyz  = (const float*)d_in[0];
    const float* feat = (const float*)d_in[1];
    const float* w0   = (const float*)d_in[2];
    const float* w1   = (const float*)d_in[3];
    const float* w2   = (const float*)d_in[4];
    const float* g0   = (const float*)d_in[5];
    const float* g1   = (const float*)d_in[6];
    const float* g2   = (const float*)d_in[7];
    const float* b0   = (const float*)d_in[8];
    const float* b1   = (const float*)d_in[9];
    const float* b2   = (const float*)d_in[10];
    float* out = (float*)d_out;

    const int SM1 = (2*128*LD1 + 2*64*LD1) * 2;     /* 67584 */
    const int SM2 = (2*128*LD2 + 2*64*LD2) * 2;     /* 55296 */
    const int SM3 = (2*128*LD2 + 2*128*LD2) * 2;    /* 73728 */
    cudaFuncSetAttribute(conv1_mma, cudaFuncAttributeMaxDynamicSharedMemorySize, SM1);
    cudaFuncSetAttribute(conv2_mma, cudaFuncAttributeMaxDynamicSharedMemorySize, SM2);
    cudaFuncSetAttribute(conv3_mma, cudaFuncAttributeMaxDynamicSharedMemorySize, SM3);

    init_kernel<<<1, 128>>>();
    fps_kernel<<<BB, 1024>>>(xyz, out);
    knn_kernel<<<NQ, 128>>>(xyz);

    /* fused per-layer launches: blocks 0..2047 s=0, 2048..6143 s=1, rest s=2 */
    const int NB = 2048 + 4096 + 8192;   /* 14336 */
    conv1_mma<<<NB, 256, SM1>>>(xyz, feat, w0);
    conv2_mma<<<NB, 256, SM2>>>(w1, g0, b0);
    conv3_mma<<<NB, 256, SM3>>>(w2, g1, b1);
    finalize_kernel<<<NQ, 384>>>(out, g2, b2);
}

// round 17
// speedup vs baseline: 1.0528x; 1.0179x over previous
#include <cuda_runtime.h>
#include <cuda_bf16.h>
#include <mma.h>
#include <cstdint>

using namespace nvcuda;

#define BB 16
#define NN 4096
#define SS 1024
#define NQ (BB*SS)
#define KMAX 64
#define CIN 67
#define CF  64

/* ---------------- scratch (device globals; no allocation allowed) -------- */
__device__ int    g_knn[NQ*KMAX];
__device__ float  g_newxyz[NQ*3];
__device__ int    g_prog[BB];
#define B1OFF0 0u
#define B1OFF1 (16384u*16u*64u)
#define B1OFF2 (B1OFF1 + 16384u*32u*64u)
#define B1TOT  (B1OFF2 + 16384u*64u*64u)
__device__ float  g_buf1[B1TOT];
__device__ float  g_buf2[B1TOT];
__device__ float  g_max[(size_t)3*NQ*128];
__device__ float  g_min[(size_t)3*NQ*128];
__device__ double g_sum[3][3][128];   /* [scale][layer][chan] */
__device__ double g_sq[3][3][128];

__device__ __forceinline__ void decode_scale(int bid, int &s, int &tile)
{
    if (bid < 2048)      { s = 0; tile = bid; }
    else if (bid < 6144) { s = 1; tile = bid - 2048; }
    else                 { s = 2; tile = bid - 6144; }
}
__device__ __forceinline__ unsigned scale_boff(int s)
{
    return (s == 0) ? B1OFF0 : (s == 1) ? B1OFF1 : B1OFF2;
}

__device__ __forceinline__ void split2(float a, float b, unsigned &hi, unsigned &lo)
{
    __nv_bfloat16 ah = __float2bfloat16(a), bh = __float2bfloat16(b);
    float ar = a - __bfloat162float(ah), br = b - __bfloat162float(bh);
    __nv_bfloat16 al = __float2bfloat16(ar), bl = __float2bfloat16(br);
    hi = (unsigned)__bfloat16_as_ushort(ah) | ((unsigned)__bfloat16_as_ushort(bh) << 16);
    lo = (unsigned)__bfloat16_as_ushort(al) | ((unsigned)__bfloat16_as_ushort(bl) << 16);
}

__device__ __forceinline__ void bn_coeff(int s, int layer, int c, double invn,
                                         const float* gamma, const float* beta,
                                         float &scl, float &shf)
{
    double sv = g_sum[s][layer][c], q2 = g_sq[s][layer][c];
    double mu = sv * invn;
    double var = q2 * invn - mu * mu;
    float rstd = rsqrtf((float)var + 1e-5f);
    scl = gamma[c] * rstd;
    shf = beta[c] - (float)mu * scl;
}

/* --------------------------- init ---------------------------------------- */
__global__ void init_kernel()
{
    int t = threadIdx.x;
    if (t < 128) {
#pragma unroll
        for (int s = 0; s < 3; s++)
#pragma unroll
            for (int l = 0; l < 3; l++) {
                g_sum[s][l][t] = 0.0;
                g_sq[s][l][t]  = 0.0;
            }
    }
    if (t < BB) g_prog[t] = 0;
}

/* ---------- fused FPS + kNN (producer/consumer, one kernel) -------------- */
__device__ __forceinline__ unsigned mono_f32(float v)
{
    unsigned u = __float_as_uint(v);
    return (u & 0x80000000u) ? ~u : (u | 0x80000000u);
}
__device__ __forceinline__ void barx(int id)
{
    asm volatile("bar.sync %0, 128;" :: "r"(id) : "memory");
}

__global__ void __launch_bounds__(1024, 1) fpsknn_kernel(const float* __restrict__ xyz,
                                                         float* __restrict__ out_newxyz)
{
    __shared__ unsigned long long wb[2][32];              /* FPS */
    __shared__ unsigned hist8[8][256];                    /* kNN */
    __shared__ unsigned long long arr8[8][64];
    __shared__ unsigned long long sK8[8];
    __shared__ int sbin8[8], sr8[8], scnt8[8], spos8[8];

    if (blockIdx.x < BB) {
        /* ------------------------- FPS producer -------------------------- */
        const int b = blockIdx.x;
        const int t = threadIdx.x;
        const int lane = t & 31, wid = t >> 5;
        const float* X = xyz + (size_t)b*NN*3;

        float px[4], py[4], pz[4], dd[4];
#pragma unroll
        for (int j = 0; j < 4; j++) {
            int p = t + 1024*j;
            px[j] = X[p*3+0]; py[j] = X[p*3+1]; pz[j] = X[p*3+2];
            dd[j] = 1e10f;
        }
        int far = 0;

        for (int it = 0; it < SS; ++it) {
            const int par = it & 1;
            float cx = X[far*3+0], cy = X[far*3+1], cz = X[far*3+2];
            if (t == 0) {
                int o = b*SS + it;
                out_newxyz[o*3+0] = cx; out_newxyz[o*3+1] = cy; out_newxyz[o*3+2] = cz;
                g_newxyz[o*3+0]  = cx; g_newxyz[o*3+1]  = cy; g_newxyz[o*3+2]  = cz;
                if ((it & 15) == 15)
                    asm volatile("st.release.gpu.global.b32 [%0], %1;"
                                 :: "l"(g_prog + b), "r"(it + 1) : "memory");
            }
            unsigned long long best = 0ull;
#pragma unroll
            for (int j = 0; j < 4; j++) {
                float dx = px[j]-cx, dy = py[j]-cy, dz = pz[j]-cz;
                float d  = fmaf(dz, dz, fmaf(dy, dy, dx*dx));
                dd[j] = fminf(dd[j], d);
                int p = t + 1024*j;
                unsigned long long key =
                    (((unsigned long long)__float_as_uint(dd[j])) << 32) | (unsigned)(NN-1-p);
                best = (key > best) ? key : best;
            }
#pragma unroll
            for (int o = 16; o; o >>= 1) {
                unsigned long long v = __shfl_xor_sync(0xffffffffu, best, o);
                if (v > best) best = v;
            }
            if (lane == 0) wb[par][wid] = best;
            __syncthreads();
            unsigned long long v = wb[par][lane];
#pragma unroll
            for (int o = 16; o; o >>= 1) {
                unsigned long long u = __shfl_xor_sync(0xffffffffu, v, o);
                if (u > v) v = u;
            }
            far = NN - 1 - (int)(v & 0xffffffffu);
        }
        return;
    }

    /* --------------------------- kNN consumers --------------------------- */
    const int grp = threadIdx.x >> 7;
    const int t   = threadIdx.x & 127;
    const int lane = t & 31;
    const int q = (blockIdx.x - BB)*8 + grp;
    const int b = q >> 10;
    const float* X = xyz + (size_t)b*NN*3;

    unsigned* hist = hist8[grp];
    unsigned long long* arr = arr8[grp];

    if (t == 0) {
        const int qi = q & 1023;
        int p;
        do {
            asm volatile("ld.acquire.gpu.global.b32 %0, [%1];"
                         : "=r"(p) : "l"(g_prog + b) : "memory");
            if (p <= qi) __nanosleep(128);
        } while (p <= qi);
    }
    barx(grp);

    const float qx = g_newxyz[q*3+0], qy = g_newxyz[q*3+1], qz = g_newxyz[q*3+2];
    const float qq = qx*qx + qy*qy + qz*qz;

    unsigned mk[32];
#pragma unroll 8
    for (int i = 0; i < 32; i++) {
        int p = t + 128*i;
        float x = X[p*3+0], y = X[p*3+1], z = X[p*3+2];
        float pp  = x*x + y*y + z*z;
        float dot = qx*x + qy*y + qz*z;
        float d2  = qq + pp - 2.0f*dot;
        mk[i] = mono_f32(d2);
    }

    unsigned long long prefix = 0ull, pmask = 0ull;
    int r = KMAX;
    for (int shift = 56; shift >= 0; shift -= 8) {
        hist[t] = 0u; hist[t+128] = 0u;
        barx(grp);
#pragma unroll 8
        for (int i = 0; i < 32; i++) {
            unsigned long long k = ((unsigned long long)mk[i] << 32) | (unsigned)(t + 128*i);
            if ((k & pmask) == prefix)
                atomicAdd(&hist[(unsigned)(k >> shift) & 255u], 1u);
        }
        barx(grp);
        if (t < 32) {
            unsigned part = 0;
#pragma unroll
            for (int i = 0; i < 8; i++) part += hist[t*8 + i];
            unsigned cum = part;
#pragma unroll
            for (int o = 1; o < 32; o <<= 1) {
                unsigned v = __shfl_up_sync(0xffffffffu, cum, o);
                if (lane >= o) cum += v;
            }
            unsigned cb = cum - part;
            bool has = (cb < (unsigned)r) && ((unsigned)r <= cum);
            unsigned mball = __ballot_sync(0xffffffffu, has);
            if (t == __ffs(mball) - 1) {
                int rr = r - (int)cb;
                int bb = t*8;
                for (;;) {
                    unsigned h = hist[bb];
                    if (rr <= (int)h) { scnt8[grp] = (int)h; break; }
                    rr -= (int)h; bb++;
                }
                sbin8[grp] = bb; sr8[grp] = rr;
            }
        }
        barx(grp);
        prefix |= ((unsigned long long)(unsigned)sbin8[grp]) << shift;
        pmask  |= (255ull << shift);
        r = sr8[grp];
        int cnt = scnt8[grp];
        barx(grp);
        if (cnt == 1) break;
    }

#pragma unroll 8
    for (int i = 0; i < 32; i++) {
        unsigned long long k = ((unsigned long long)mk[i] << 32) | (unsigned)(t + 128*i);
        if ((k & pmask) == prefix) sK8[grp] = k;
    }
    if (t == 0) spos8[grp] = 0;
    barx(grp);
    const unsigned long long K64 = sK8[grp];

#pragma unroll 8
    for (int i = 0; i < 32; i++) {
        unsigned long long k = ((unsigned long long)mk[i] << 32) | (unsigned)(t + 128*i);
        if (k <= K64) {
            int pos = atomicAdd(&spos8[grp], 1);
            arr[pos] = k;
        }
    }
    barx(grp);

    for (int k2 = 2; k2 <= 64; k2 <<= 1)
        for (int j = k2 >> 1; j > 0; j >>= 1) {
            if (t < 64) {
                int ixj = t ^ j;
                if (ixj > t) {
                    unsigned long long a = arr[t], c = arr[ixj];
                    bool up = ((t & k2) == 0);
                    if ((a > c) == up) { arr[t] = c; arr[ixj] = a; }
                }
            }
            barx(grp);
        }

    if (t < 64) g_knn[q*KMAX + t] = (int)(arr[t] & 0xffffffffu);
}

/* ================== WMMA bf16 (hi/lo split) conv kernels ================= */
#define LD1 88
#define LD2 72

/* ---- conv1: gather+concat + 80->64 --------------------------------------*/
__global__ void __launch_bounds__(256, 2) conv1_mma(const float* __restrict__ xyz,
                                                    const float* __restrict__ feat,
                                                    const float* __restrict__ w0)
{
    extern __shared__ char dyn[];
    __nv_bfloat16* Ah = (__nv_bfloat16*)dyn;          /* [128][LD1] */
    __nv_bfloat16* Al = Ah + 128*LD1;
    __nv_bfloat16* Bh = Al + 128*LD1;                 /* [64][LD1]  */
    __nv_bfloat16* Bl = Bh + 64*LD1;
    float* Cs = (float*)dyn;                          /* reuse: [128][64] */
    __shared__ float ps[4][64], pq[4][64];

    const int t = threadIdx.x;
    int s, tile;
    decode_scale(blockIdx.x, s, tile);
    const int lgk = 4 + s;
    const unsigned boff = scale_boff(s);
    const float* W = w0 + (size_t)s*64*CIN;
    const int wid = t >> 5;

    {
        const int r = t >> 1, sub = t & 1;
        const int gr = tile*128 + r;
        const int q  = gr >> lgk;
        const int j  = gr & ((1 << lgk) - 1);
        const int n  = g_knn[q*KMAX + j];
        const int b  = q >> 10;
        const float* fp = feat + (size_t)(b*NN + n)*CF;
        unsigned* ah = (unsigned*)(Ah + r*LD1);
        unsigned* al = (unsigned*)(Al + r*LD1);
#pragma unroll
        for (int jj = sub*8; jj < sub*8 + 8; jj++) {
            float4 v = *(const float4*)(fp + jj*4);
            unsigned h0, l0, h1, l1;
            split2(v.x, v.y, h0, l0); split2(v.z, v.w, h1, l1);
            ah[jj*2]   = h0; ah[jj*2+1] = h1;
            al[jj*2]   = l0; al[jj*2+1] = l1;
        }
        if (sub) {
            const float* xp = xyz + (size_t)(b*NN + n)*3;
            float dx = xp[0]-g_newxyz[q*3+0], dy = xp[1]-g_newxyz[q*3+1], dz = xp[2]-g_newxyz[q*3+2];
            unsigned h0, l0, h1, l1;
            split2(dx, dy, h0, l0); split2(dz, 0.f, h1, l1);
            ah[32] = h0; ah[33] = h1; al[32] = l0; al[33] = l1;
#pragma unroll
            for (int z = 34; z < 40; z++) { ah[z] = 0u; al[z] = 0u; }
        }
    }
    if (t < 128) {
        const int n = t >> 1, sub = t & 1;
        const float* w = W + n*CIN;
        unsigned* bh = (unsigned*)(Bh + n*LD1);
        unsigned* bl = (unsigned*)(Bl + n*LD1);
#pragma unroll
        for (int jj = sub*16; jj < sub*16 + 16; jj++) {
            unsigned h, l;
            split2(w[3 + jj*2], w[3 + jj*2 + 1], h, l);
            bh[jj] = h; bl[jj] = l;
        }
        if (sub) {
            unsigned h0, l0, h1, l1;
            split2(w[0], w[1], h0, l0); split2(w[2], 0.f, h1, l1);
            bh[32] = h0; bh[33] = h1; bl[32] = l0; bl[33] = l1;
#pragma unroll
            for (int z = 34; z < 40; z++) { bh[z] = 0u; bl[z] = 0u; }
        }
    }
    __syncthreads();

    const int rowg = wid >> 1, colg = wid & 1;
    wmma::fragment<wmma::accumulator, 16, 16, 16, float> acc[2][2];
#pragma unroll
    for (int i = 0; i < 2; i++)
#pragma unroll
        for (int j = 0; j < 2; j++) wmma::fill_fragment(acc[i][j], 0.f);

#pragma unroll
    for (int ks = 0; ks < 5; ks++) {
        wmma::fragment<wmma::matrix_a, 16, 16, 16, __nv_bfloat16, wmma::row_major> afh[2], afl[2];
        wmma::fragment<wmma::matrix_b, 16, 16, 16, __nv_bfloat16, wmma::col_major> bfh[2];
#pragma unroll
        for (int i = 0; i < 2; i++) {
            wmma::load_matrix_sync(afh[i], Ah + (rowg*32 + i*16)*LD1 + ks*16, LD1);
            wmma::load_matrix_sync(afl[i], Al + (rowg*32 + i*16)*LD1 + ks*16, LD1);
        }
#pragma unroll
        for (int j = 0; j < 2; j++)
            wmma::load_matrix_sync(bfh[j], Bh + (colg*32 + j*16)*LD1 + ks*16, LD1);
#pragma unroll
        for (int i = 0; i < 2; i++)
#pragma unroll
            for (int j = 0; j < 2; j++) {
                wmma::mma_sync(acc[i][j], afh[i], bfh[j], acc[i][j]);
                wmma::mma_sync(acc[i][j], afl[i], bfh[j], acc[i][j]);
            }
    }
#pragma unroll
    for (int ks = 0; ks < 5; ks++) {
        wmma::fragment<wmma::matrix_a, 16, 16, 16, __nv_bfloat16, wmma::row_major> af[2];
        wmma::fragment<wmma::matrix_b, 16, 16, 16, __nv_bfloat16, wmma::col_major> bf[2];
#pragma unroll
        for (int i = 0; i < 2; i++)
            wmma::load_matrix_sync(af[i], Ah + (rowg*32 + i*16)*LD1 + ks*16, LD1);
#pragma unroll
        for (int j = 0; j < 2; j++)
            wmma::load_matrix_sync(bf[j], Bl + (colg*32 + j*16)*LD1 + ks*16, LD1);
#pragma unroll
        for (int i = 0; i < 2; i++)
#pragma unroll
            for (int j = 0; j < 2; j++)
                wmma::mma_sync(acc[i][j], af[i], bf[j], acc[i][j]);
    }
    __syncthreads();
#pragma unroll
    for (int i = 0; i < 2; i++)
#pragma unroll
        for (int j = 0; j < 2; j++)
            wmma::store_matrix_sync(Cs + (rowg*32 + i*16)*64 + colg*32 + j*16,
                                    acc[i][j], 64, wmma::mem_row_major);
    __syncthreads();

    float* bufOut = g_buf1 + boff;
    const size_t base = (size_t)tile*128*64;
    for (int i = t*4; i < 128*64; i += 1024)
        *(float4*)(bufOut + base + i) = *(const float4*)(Cs + i);

    {
        const int c = t & 63, rq = t >> 6;
        float sv = 0.f, q2 = 0.f;
#pragma unroll 8
        for (int r0 = 0; r0 < 32; r0++) {
            float v = Cs[(rq*32 + r0)*64 + c];
            sv += v; q2 = fmaf(v, v, q2);
        }
        ps[rq][c] = sv; pq[rq][c] = q2;
    }
    __syncthreads();
    if (t < 64) {
        atomicAdd(&g_sum[s][0][t], (double)(ps[0][t]+ps[1][t]+ps[2][t]+ps[3][t]));
        atomicAdd(&g_sq[s][0][t],  (double)(pq[0][t]+pq[1][t]+pq[2][t]+pq[3][t]));
    }
}

/* ---- conv2: BN+ReLU load + 64->64 ---------------------------------------*/
__global__ void __launch_bounds__(256, 2) conv2_mma(const float* __restrict__ w1,
                                                    const float* __restrict__ g0,
                                                    const float* __restrict__ b0)
{
    extern __shared__ char dyn[];
    __nv_bfloat16* Ah = (__nv_bfloat16*)dyn;
    __nv_bfloat16* Al = Ah + 128*LD2;
    __nv_bfloat16* Bh = Al + 128*LD2;
    __nv_bfloat16* Bl = Bh + 64*LD2;
    float* Cs = (float*)dyn;
    __shared__ float sc[64], sh[64], ps[4][64], pq[4][64];

    const int t = threadIdx.x;
    int s, tile;
    decode_scale(blockIdx.x, s, tile);
    const unsigned boff = scale_boff(s);
    const float* W = w1 + (size_t)s*64*64;
    const double invn = 1.0 / (double)(NQ * (16 << s));
    const int wid = t >> 5;

    if (t < 64) bn_coeff(s, 0, t, invn, g0 + s*64, b0 + s*64, sc[t], sh[t]);
    __syncthreads();

    {
        const int r = t >> 1, sub = t & 1;
        const float* ip = g_buf1 + boff + ((size_t)tile*128 + r)*64;
        unsigned* ah = (unsigned*)(Ah + r*LD2);
        unsigned* al = (unsigned*)(Al + r*LD2);
#pragma unroll
        for (int jj = sub*8; jj < sub*8 + 8; jj++) {
            float4 v = *(const float4*)(ip + jj*4);
            int c0 = jj*4;
            float a = fmaxf(fmaf(v.x, sc[c0+0], sh[c0+0]), 0.f);
            float b = fmaxf(fmaf(v.y, sc[c0+1], sh[c0+1]), 0.f);
            float c = fmaxf(fmaf(v.z, sc[c0+2], sh[c0+2]), 0.f);
            float d = fmaxf(fmaf(v.w, sc[c0+3], sh[c0+3]), 0.f);
            unsigned h0, l0, h1, l1;
            split2(a, b, h0, l0); split2(c, d, h1, l1);
            ah[jj*2] = h0; ah[jj*2+1] = h1;
            al[jj*2] = l0; al[jj*2+1] = l1;
        }
    }
    if (t < 128) {
        const int n = t >> 1, sub = t & 1;
        const float* w = W + n*64;
        unsigned* bh = (unsigned*)(Bh + n*LD2);
        unsigned* bl = (unsigned*)(Bl + n*LD2);
#pragma unroll
        for (int jj = sub*8; jj < sub*8 + 8; jj++) {
            float4 v = *(const float4*)(w + jj*4);
            unsigned h0, l0, h1, l1;
            split2(v.x, v.y, h0, l0); split2(v.z, v.w, h1, l1);
            bh[jj*2] = h0; bh[jj*2+1] = h1;
            bl[jj*2] = l0; bl[jj*2+1] = l1;
        }
    }
    __syncthreads();

    const int rowg = wid >> 1, colg = wid & 1;
    wmma::fragment<wmma::accumulator, 16, 16, 16, float> acc[2][2];
#pragma unroll
    for (int i = 0; i < 2; i++)
#pragma unroll
        for (int j = 0; j < 2; j++) wmma::fill_fragment(acc[i][j], 0.f);

#pragma unroll
    for (int ks = 0; ks < 4; ks++) {
        wmma::fragment<wmma::matrix_a, 16, 16, 16, __nv_bfloat16, wmma::row_major> afh[2], afl[2];
        wmma::fragment<wmma::matrix_b, 16, 16, 16, __nv_bfloat16, wmma::col_major> bfh[2];
#pragma unroll
        for (int i = 0; i < 2; i++) {
            wmma::load_matrix_sync(afh[i], Ah + (rowg*32 + i*16)*LD2 + ks*16, LD2);
            wmma::load_matrix_sync(afl[i], Al + (rowg*32 + i*16)*LD2 + ks*16, LD2);
        }
#pragma unroll
        for (int j = 0; j < 2; j++)
            wmma::load_matrix_sync(bfh[j], Bh + (colg*32 + j*16)*LD2 + ks*16, LD2);
#pragma unroll
        for (int i = 0; i < 2; i++)
#pragma unroll
            for (int j = 0; j < 2; j++) {
                wmma::mma_sync(acc[i][j], afh[i], bfh[j], acc[i][j]);
                wmma::mma_sync(acc[i][j], afl[i], bfh[j], acc[i][j]);
            }
    }
#pragma unroll
    for (int ks = 0; ks < 4; ks++) {
        wmma::fragment<wmma::matrix_a, 16, 16, 16, __nv_bfloat16, wmma::row_major> af[2];
        wmma::fragment<wmma::matrix_b, 16, 16, 16, __nv_bfloat16, wmma::col_major> bf[2];
#pragma unroll
        for (int i = 0; i < 2; i++)
            wmma::load_matrix_sync(af[i], Ah + (rowg*32 + i*16)*LD2 + ks*16, LD2);
#pragma unroll
        for (int j = 0; j < 2; j++)
            wmma::load_matrix_sync(bf[j], Bl + (colg*32 + j*16)*LD2 + ks*16, LD2);
#pragma unroll
        for (int i = 0; i < 2; i++)
#pragma unroll
            for (int j = 0; j < 2; j++)
                wmma::mma_sync(acc[i][j], af[i], bf[j], acc[i][j]);
    }
    __syncthreads();
#pragma unroll
    for (int i = 0; i < 2; i++)
#pragma unroll
        for (int j = 0; j < 2; j++)
            wmma::store_matrix_sync(Cs + (rowg*32 + i*16)*64 + colg*32 + j*16,
                                    acc[i][j], 64, wmma::mem_row_major);
    __syncthreads();

    float* bufOut = g_buf2 + boff;
    const size_t base = (size_t)tile*128*64;
    for (int i = t*4; i < 128*64; i += 1024)
        *(float4*)(bufOut + base + i) = *(const float4*)(Cs + i);

    {
        const int c = t & 63, rq = t >> 6;
        float sv = 0.f, q2 = 0.f;
#pragma unroll 8
        for (int r0 = 0; r0 < 32; r0++) {
            float v = Cs[(rq*32 + r0)*64 + c];
            sv += v; q2 = fmaf(v, v, q2);
        }
        ps[rq][c] = sv; pq[rq][c] = q2;
    }
    __syncthreads();
    if (t < 64) {
        atomicAdd(&g_sum[s][1][t], (double)(ps[0][t]+ps[1][t]+ps[2][t]+ps[3][t]));
        atomicAdd(&g_sq[s][1][t],  (double)(pq[0][t]+pq[1][t]+pq[2][t]+pq[3][t]));
    }
}

/* ---- conv3: BN+ReLU load + 64->128 + per-query max/min (runtime K) ------ */
__global__ void __launch_bounds__(256, 2) conv3_mma(const float* __restrict__ w2,
                                                    const float* __restrict__ g1,
                                                    const float* __restrict__ b1)
{
    extern __shared__ char dyn[];
    __nv_bfloat16* Ah = (__nv_bfloat16*)dyn;
    __nv_bfloat16* Al = Ah + 128*LD2;
    __nv_bfloat16* Bh = Al + 128*LD2;
    __nv_bfloat16* Bl = Bh + 128*LD2;
    float* Cs = (float*)dyn;                          /* [128][128] */
    __shared__ float sc[64], sh[64], ps[2][128], pq[2][128];

    const int t = threadIdx.x;
    int s, tile;
    decode_scale(blockIdx.x, s, tile);
    const int K = 16 << s;
    const unsigned boff = scale_boff(s);
    const float* W = w2 + (size_t)s*128*64;
    const double invn = 1.0 / (double)(NQ * K);
    const int wid = t >> 5;

    if (t < 64) bn_coeff(s, 1, t, invn, g1 + s*64, b1 + s*64, sc[t], sh[t]);
    __syncthreads();

    {
        const int r = t >> 1, sub = t & 1;
        const float* ip = g_buf2 + boff + ((size_t)tile*128 + r)*64;
        unsigned* ah = (unsigned*)(Ah + r*LD2);
        unsigned* al = (unsigned*)(Al + r*LD2);
#pragma unroll
        for (int jj = sub*8; jj < sub*8 + 8; jj++) {
            float4 v = *(const float4*)(ip + jj*4);
            int c0 = jj*4;
            float a = fmaxf(fmaf(v.x, sc[c0+0], sh[c0+0]), 0.f);
            float b = fmaxf(fmaf(v.y, sc[c0+1], sh[c0+1]), 0.f);
            float c = fmaxf(fmaf(v.z, sc[c0+2], sh[c0+2]), 0.f);
            float d = fmaxf(fmaf(v.w, sc[c0+3], sh[c0+3]), 0.f);
            unsigned h0, l0, h1, l1;
            split2(a, b, h0, l0); split2(c, d, h1, l1);
            ah[jj*2] = h0; ah[jj*2+1] = h1;
            al[jj*2] = l0; al[jj*2+1] = l1;
        }
    }
    {
        const int n = t >> 1, sub = t & 1;
        const float* w = W + (size_t)n*64;
        unsigned* bh = (unsigned*)(Bh + n*LD2);
        unsigned* bl = (unsigned*)(Bl + n*LD2);
#pragma unroll
        for (int jj = sub*8; jj < sub*8 + 8; jj++) {
            float4 v = *(const float4*)(w + jj*4);
            unsigned h0, l0, h1, l1;
            split2(v.x, v.y, h0, l0); split2(v.z, v.w, h1, l1);
            bh[jj*2] = h0; bh[jj*2+1] = h1;
            bl[jj*2] = l0; bl[jj*2+1] = l1;
        }
    }
    __syncthreads();

    const int rowg = wid >> 1, colg = wid & 1;
    wmma::fragment<wmma::accumulator, 16, 16, 16, float> acc[2][4];
#pragma unroll
    for (int i = 0; i < 2; i++)
#pragma unroll
        for (int j = 0; j < 4; j++) wmma::fill_fragment(acc[i][j], 0.f);

#pragma unroll
    for (int ks = 0; ks < 4; ks++) {
        wmma::fragment<wmma::matrix_a, 16, 16, 16, __nv_bfloat16, wmma::row_major> afh[2], afl[2];
#pragma unroll
        for (int i = 0; i < 2; i++) {
            wmma::load_matrix_sync(afh[i], Ah + (rowg*32 + i*16)*LD2 + ks*16, LD2);
            wmma::load_matrix_sync(afl[i], Al + (rowg*32 + i*16)*LD2 + ks*16, LD2);
        }
#pragma unroll
        for (int j = 0; j < 4; j++) {
            wmma::fragment<wmma::matrix_b, 16, 16, 16, __nv_bfloat16, wmma::col_major> bf;
            wmma::load_matrix_sync(bf, Bh + (colg*64 + j*16)*LD2 + ks*16, LD2);
#pragma unroll
            for (int i = 0; i < 2; i++) {
                wmma::mma_sync(acc[i][j], afh[i], bf, acc[i][j]);
                wmma::mma_sync(acc[i][j], afl[i], bf, acc[i][j]);
            }
        }
    }
#pragma unroll
    for (int ks = 0; ks < 4; ks++) {
        wmma::fragment<wmma::matrix_a, 16, 16, 16, __nv_bfloat16, wmma::row_major> af[2];
#pragma unroll
        for (int i = 0; i < 2; i++)
            wmma::load_matrix_sync(af[i], Ah + (rowg*32 + i*16)*LD2 + ks*16, LD2);
#pragma unroll
        for (int j = 0; j < 4; j++) {
            wmma::fragment<wmma::matrix_b, 16, 16, 16, __nv_bfloat16, wmma::col_major> bf;
            wmma::load_matrix_sync(bf, Bl + (colg*64 + j*16)*LD2 + ks*16, LD2);
#pragma unroll
            for (int i = 0; i < 2; i++)
                wmma::mma_sync(acc[i][j], af[i], bf, acc[i][j]);
        }
    }
    __syncthreads();
#pragma unroll
    for (int i = 0; i < 2; i++)
#pragma unroll
        for (int j = 0; j < 4; j++)
            wmma::store_matrix_sync(Cs + (rowg*32 + i*16)*128 + colg*64 + j*16,
                                    acc[i][j], 128, wmma::mem_row_major);
    __syncthreads();

    {
        const int c = t & 127, rh = t >> 7;
        float sv = 0.f, q2 = 0.f;
#pragma unroll 8
        for (int r0 = 0; r0 < 64; r0++) {
            float v = Cs[(rh*64 + r0)*128 + c];
            sv += v; q2 = fmaf(v, v, q2);
        }
        ps[rh][c] = sv; pq[rh][c] = q2;
    }
    {
        const int c = t & 127, g = t >> 7;
        const int nq_tile = 128 / K;
        float* gmax = g_max + (size_t)s*NQ*128;
        float* gmin = g_min + (size_t)s*NQ*128;
        for (int qi = g; qi < nq_tile; qi += 2) {
            float mx = -3.4e38f, mn = 3.4e38f;
#pragma unroll 8
            for (int r0 = 0; r0 < K; r0++) {
                float v = Cs[(qi*K + r0)*128 + c];
                mx = fmaxf(mx, v); mn = fminf(mn, v);
            }
            const int q = tile*nq_tile + qi;
            gmax[q*128 + c] = mx;
            gmin[q*128 + c] = mn;
        }
    }
    __syncthreads();
    if (t < 128) {
        atomicAdd(&g_sum[s][2][t], (double)(ps[0][t] + ps[1][t]));
        atomicAdd(&g_sq[s][2][t],  (double)(pq[0][t] + pq[1][t]));
    }
}

/* -------- finalize (all scales): BN + sign-aware max/min + ReLU ---------- */
__global__ void __launch_bounds__(384) finalize_kernel(float* __restrict__ out,
                                                       const float* __restrict__ g2,
                                                       const float* __restrict__ b2)
{
    const int q = blockIdx.x;
    const int t = threadIdx.x;
    const int s = t >> 7, c = t & 127;
    const double invn = 1.0 / (double)(NQ * (16 << s));
    float scl, shf;
    bn_coeff(s, 2, c, invn, g2 + s*128, b2 + s*128, scl, shf);
    const float* gmax = g_max + (size_t)s*NQ*128;
    const float* gmin = g_min + (size_t)s*NQ*128;
    float sel = (scl >= 0.f) ? gmax[q*128 + c] : gmin[q*128 + c];
    out[(size_t)NQ*3 + (size_t)q*384 + t] = fmaxf(fmaf(sel, scl, shf), 0.f);
}

/* ------------------------------ driver ----------------------------------- */
extern "C" void kernel_launch(void* const* d_in, const int* in_sizes, int n_in,
                              void* d_out, int out_size)
{
    const float* xyz  = (const float*)d_in[0];
    const float* feat = (const float*)d_in[1];
    const float* w0   = (const float*)d_in[2];
    const float* w1   = (const float*)d_in[3];
    const float* w2   = (const float*)d_in[4];
    const float* g0   = (const float*)d_in[5];
    const float* g1   = (const float*)d_in[6];
    const float* g2   = (const float*)d_in[7];
    const float* b0   = (const float*)d_in[8];
    const float* b1   = (const float*)d_in[9];
    const float* b2   = (const float*)d_in[10];
    float* out = (float*)d_out;

    const int SM1 = (2*128*LD1 + 2*64*LD1) * 2;     /* 67584 */
    const int SM2 = (2*128*LD2 + 2*64*LD2) * 2;     /* 55296 */
    const int SM3 = (2*128*LD2 + 2*128*LD2) * 2;    /* 73728 */
    cudaFuncSetAttribute(conv1_mma, cudaFuncAttributeMaxDynamicSharedMemorySize, SM1);
    cudaFuncSetAttribute(conv2_mma, cudaFuncAttributeMaxDynamicSharedMemorySize, SM2);
    cudaFuncSetAttribute(conv3_mma, cudaFuncAttributeMaxDynamicSharedMemorySize, SM3);

    init_kernel<<<1, 128>>>();
    fpsknn_kernel<<<BB + NQ/8, 1024>>>(xyz, out);

    const int NB = 2048 + 4096 + 8192;   /* 14336 */
    conv1_mma<<<NB, 256, SM1>>>(xyz, feat, w0);
    conv2_mma<<<NB, 256, SM2>>>(w1, g0, b0);
    conv3_mma<<<NB, 256, SM3>>>(w2, g1, b1);
    finalize_kernel<<<NQ, 384>>>(out, g2, b2);
}